// round 1
// baseline (speedup 1.0000x reference)
#include <cuda_runtime.h>
#include <cstdint>

// Problem constants (fixed shapes per reference)
namespace cfg {
constexpr int B  = 4;
constexpr int S  = 2048;
constexpr int D  = 768;
constexpr int H  = 12;
constexpr int HD = 64;            // head dim
constexpr int MTOK = B * S;       // 8192 token rows
constexpr int NQKV = 3 * D;       // 2304
constexpr int BH   = B * H;       // 48
}

// -------- scratch (static device globals; no runtime allocation) --------
__device__ float g_QKV[(size_t)cfg::MTOK * cfg::NQKV];          // 75.5 MB
__device__ float g_Q  [(size_t)cfg::BH * cfg::S * cfg::HD];     // 25.2 MB
__device__ float g_K  [(size_t)cfg::BH * cfg::S * cfg::HD];
__device__ float g_V  [(size_t)cfg::BH * cfg::S * cfg::HD];
__device__ float g_SV [(size_t)cfg::BH * cfg::S * cfg::HD];     // V suffix sums
__device__ float g_Tot[cfg::BH * 4 * cfg::HD];                  // per-segment totals
__device__ float g_A  [(size_t)cfg::MTOK * cfg::D];             // attention output

// ============================================================================
// SGEMM: C[M,N] = A[M,K] @ B[K,N] + bias[N]   (row-major, M%128==0, N%128==0, K%8==0)
// 128x128 tile, BK=8, 256 threads, 8x8 per thread with split-tile (4 + 4 at +64)
// ============================================================================
__global__ void __launch_bounds__(256) sgemm_bias_kernel(
    const float* __restrict__ A, const float* __restrict__ Bm,
    const float* __restrict__ bias, float* __restrict__ C,
    int M, int N, int K)
{
    __shared__ float As[8][128];   // As[k][m]
    __shared__ float Bs[8][128];   // Bs[k][n]
    const int tid = threadIdx.x;
    const int tx  = tid & 15;      // 16 col-groups
    const int ty  = tid >> 4;      // 16 row-groups
    const int m0  = blockIdx.y * 128;
    const int n0  = blockIdx.x * 128;

    // A loader: thread -> (row lm, 4 k's)
    const int lm  = tid >> 1;            // 0..127
    const int lk  = (tid & 1) * 4;       // 0 or 4
    // B loader: thread -> (k row lbk, 4 n's)
    const int lbk = tid >> 5;            // 0..7
    const int lbn = (tid & 31) * 4;      // 0..124

    float acc[8][8];
#pragma unroll
    for (int i = 0; i < 8; i++)
#pragma unroll
        for (int j = 0; j < 8; j++) acc[i][j] = 0.f;

    for (int k0 = 0; k0 < K; k0 += 8) {
        float4 av = *(const float4*)(A  + (size_t)(m0 + lm) * K + (k0 + lk));
        float4 bv = *(const float4*)(Bm + (size_t)(k0 + lbk) * N + (n0 + lbn));
        As[lk + 0][lm] = av.x;
        As[lk + 1][lm] = av.y;
        As[lk + 2][lm] = av.z;
        As[lk + 3][lm] = av.w;
        *(float4*)&Bs[lbk][lbn] = bv;
        __syncthreads();
#pragma unroll
        for (int kk = 0; kk < 8; kk++) {
            float a[8], b[8];
#pragma unroll
            for (int i = 0; i < 4; i++) {
                a[i]     = As[kk][ty * 4 + i];
                a[i + 4] = As[kk][64 + ty * 4 + i];
            }
#pragma unroll
            for (int j = 0; j < 4; j++) {
                b[j]     = Bs[kk][tx * 4 + j];
                b[j + 4] = Bs[kk][64 + tx * 4 + j];
            }
#pragma unroll
            for (int i = 0; i < 8; i++)
#pragma unroll
                for (int j = 0; j < 8; j++) acc[i][j] += a[i] * b[j];
        }
        __syncthreads();
    }

#pragma unroll
    for (int i = 0; i < 8; i++) {
        int m = m0 + ((i < 4) ? (ty * 4 + i) : (64 + ty * 4 + (i - 4)));
#pragma unroll
        for (int jh = 0; jh < 2; jh++) {
            int n = n0 + jh * 64 + tx * 4;
            float4 r;
            r.x = acc[i][jh * 4 + 0] + bias[n + 0];
            r.y = acc[i][jh * 4 + 1] + bias[n + 1];
            r.z = acc[i][jh * 4 + 2] + bias[n + 2];
            r.w = acc[i][jh * 4 + 3] + bias[n + 3];
            *(float4*)(C + (size_t)m * N + n) = r;
        }
    }
}

// ============================================================================
// Scatter QKV [B,S,3D] -> Q/K/V in [B,H,S,HD] (bh-major) layout
// ============================================================================
__global__ void scatter_qkv_kernel()
{
    int idx = blockIdx.x * 256 + threadIdx.x;
    if (idx >= cfg::BH * cfg::S * cfg::HD) return;
    int c  = idx & (cfg::HD - 1);
    int s  = (idx >> 6) & (cfg::S - 1);
    int bh = idx >> 17;                 // HD*S = 131072 = 2^17
    int h  = bh % cfg::H;
    int b  = bh / cfg::H;
    size_t src = (size_t)(b * cfg::S + s) * cfg::NQKV + h * cfg::HD + c;
    g_Q[idx] = g_QKV[src];
    g_K[idx] = g_QKV[src + cfg::D];
    g_V[idx] = g_QKV[src + 2 * cfg::D];
}

// ============================================================================
// V suffix sums: SV[bh][s][d] = sum_{k>=s} V[bh][k][d]
// pass1: 4 segments of 512 rows each, reverse scan; pass2: add later-segment totals
// ============================================================================
__global__ void suffix_pass1()
{
    int bh  = blockIdx.x >> 2;
    int seg = blockIdx.x & 3;
    int d   = threadIdx.x;  // 64
    const size_t base = (size_t)bh * cfg::S * cfg::HD;
    float acc = 0.f;
    for (int s = seg * 512 + 511; s >= seg * 512; s--) {
        acc += g_V[base + (size_t)s * cfg::HD + d];
        g_SV[base + (size_t)s * cfg::HD + d] = acc;
    }
    g_Tot[blockIdx.x * cfg::HD + d] = acc;
}

__global__ void suffix_pass2()
{
    int bh  = blockIdx.x / 3;
    int seg = blockIdx.x % 3;   // segment 3 needs no correction
    int d   = threadIdx.x;
    float add = 0.f;
    for (int s2 = seg + 1; s2 < 4; s2++) add += g_Tot[(bh * 4 + s2) * cfg::HD + d];
    const size_t base = (size_t)bh * cfg::S * cfg::HD;
    for (int s = seg * 512; s < (seg + 1) * 512; s++)
        g_SV[base + (size_t)s * cfg::HD + d] += add;
}

// ============================================================================
// Flash attention with EXACT reference mask semantics.
// Reference: w = s*mask + 1e-9*(1-mask); softmax over ALL S entries (masked
// entries carry weight exp(1e-9 - m)/Z). We GEMM only the causal lower
// triangle; masked mass is added analytically via V suffix sums:
//   out = (o_unmasked + e * SV[q+1]) / (l_unmasked + cnt * e),  e = exp(1e-9 - m)
// Identical math by softmax shift-invariance.
//
// Block: BQ=128 q-rows x full head, BK=64 keys/iter, 256 threads.
// Thread tile: 8 q-rows x 4 keys (scores) / 8 q-rows x 4 d-cols (output).
// Shared rows padded to 65 floats -> conflict-free scalar LDS per phase.
// ============================================================================
constexpr int ATTN_SMEM_FLOATS = 128 * 65 + 64 * 65 + 64 * 65 + 128 * 65;  // 24960
constexpr int ATTN_SMEM_BYTES  = ATTN_SMEM_FLOATS * 4;                      // 99840

__global__ void __launch_bounds__(256) attn_kernel()
{
    extern __shared__ float smf[];
    float* Qs = smf;                  // [128][65]
    float* Ks = Qs + 128 * 65;        // [64][65]
    float* Vs = Ks + 64 * 65;         // [64][65]
    float* Ps = Vs + 64 * 65;         // [128][65]

    const int qb = blockIdx.x;        // 0..15 (q tile of 128 rows)
    const int bh = blockIdx.y;        // 0..47
    const int b  = bh / cfg::H;
    const int h  = bh % cfg::H;
    const size_t base = (size_t)bh * cfg::S * cfg::HD;

    const int tid = threadIdx.x;
    const int tx  = tid & 15;         // key/d-col group
    const int ty  = tid >> 4;         // row group (8 rows each)

    // load Q tile (128 x 64), coalesced float4 reads, scalar smem stores
    for (int i = tid; i < 128 * 16; i += 256) {
        int r  = i >> 4;
        int c4 = (i & 15) << 2;
        float4 t = *(const float4*)(g_Q + base + (size_t)(qb * 128 + r) * cfg::HD + c4);
        float* q = &Qs[r * 65 + c4];
        q[0] = t.x; q[1] = t.y; q[2] = t.z; q[3] = t.w;
    }

    float o[8][4];
    float mi[8], li[8];
#pragma unroll
    for (int i = 0; i < 8; i++) {
        mi[i] = -1e30f;
        li[i] = 0.f;
#pragma unroll
        for (int j = 0; j < 4; j++) o[i][j] = 0.f;
    }

    const int nkb = 2 * qb + 2;       // process keys up to (qb+1)*128
    for (int kb = 0; kb < nkb; kb++) {
        __syncthreads();              // protect Ks/Vs from previous iteration readers
        for (int i = tid; i < 64 * 16; i += 256) {
            int r  = i >> 4;
            int c4 = (i & 15) << 2;
            float4 tk = *(const float4*)(g_K + base + (size_t)(kb * 64 + r) * cfg::HD + c4);
            float4 tv = *(const float4*)(g_V + base + (size_t)(kb * 64 + r) * cfg::HD + c4);
            float* kd = &Ks[r * 65 + c4];
            kd[0] = tk.x; kd[1] = tk.y; kd[2] = tk.z; kd[3] = tk.w;
            float* vd = &Vs[r * 65 + c4];
            vd[0] = tv.x; vd[1] = tv.y; vd[2] = tv.z; vd[3] = tv.w;
        }
        __syncthreads();

        // ---- S = Q K^T (8x4 per thread) ----
        float s[8][4];
#pragma unroll
        for (int i = 0; i < 8; i++)
#pragma unroll
            for (int j = 0; j < 4; j++) s[i][j] = 0.f;

#pragma unroll 4
        for (int d = 0; d < 64; d++) {
            float bk[4];
#pragma unroll
            for (int j = 0; j < 4; j++) bk[j] = Ks[(tx * 4 + j) * 65 + d];
#pragma unroll
            for (int i = 0; i < 8; i++) {
                float aq = Qs[(ty * 8 + i) * 65 + d];
#pragma unroll
                for (int j = 0; j < 4; j++) s[i][j] += aq * bk[j];
            }
        }

        // ---- causal exclusion (only last two key blocks can cross the diagonal) ----
        if (kb >= 2 * qb) {
#pragma unroll
            for (int i = 0; i < 8; i++) {
                int qg = qb * 128 + ty * 8 + i;
#pragma unroll
                for (int j = 0; j < 4; j++) {
                    int kg = kb * 64 + tx * 4 + j;
                    if (kg > qg) s[i][j] = -1e30f;   // excluded; masked mass added later
                }
            }
        }

        // ---- online softmax per row (16 lanes per row share stats) ----
#pragma unroll
        for (int i = 0; i < 8; i++) {
            float mloc = fmaxf(fmaxf(s[i][0], s[i][1]), fmaxf(s[i][2], s[i][3]));
            mloc = fmaxf(mloc, __shfl_xor_sync(0xffffffffu, mloc, 8, 16));
            mloc = fmaxf(mloc, __shfl_xor_sync(0xffffffffu, mloc, 4, 16));
            mloc = fmaxf(mloc, __shfl_xor_sync(0xffffffffu, mloc, 2, 16));
            mloc = fmaxf(mloc, __shfl_xor_sync(0xffffffffu, mloc, 1, 16));
            float mnew = fmaxf(mi[i], mloc);
            float corr = __expf(mi[i] - mnew);      // 0 on first block (mi=-1e30)
            float ps = 0.f;
#pragma unroll
            for (int j = 0; j < 4; j++) {
                float p = __expf(s[i][j] - mnew);   // 0 for excluded entries
                Ps[(ty * 8 + i) * 65 + tx * 4 + j] = p;
                ps += p;
            }
            ps += __shfl_xor_sync(0xffffffffu, ps, 8, 16);
            ps += __shfl_xor_sync(0xffffffffu, ps, 4, 16);
            ps += __shfl_xor_sync(0xffffffffu, ps, 2, 16);
            ps += __shfl_xor_sync(0xffffffffu, ps, 1, 16);
            li[i] = li[i] * corr + ps;
            mi[i] = mnew;
            o[i][0] *= corr; o[i][1] *= corr; o[i][2] *= corr; o[i][3] *= corr;
        }
        __syncwarp();   // Ps rows are produced/consumed within the same 16-lane group

        // ---- O += P V (8x4 per thread) ----
#pragma unroll 4
        for (int c = 0; c < 64; c++) {
            float vv[4];
#pragma unroll
            for (int j = 0; j < 4; j++) vv[j] = Vs[c * 65 + tx * 4 + j];
#pragma unroll
            for (int i = 0; i < 8; i++) {
                float p = Ps[(ty * 8 + i) * 65 + c];
#pragma unroll
                for (int j = 0; j < 4; j++) o[i][j] += p * vv[j];
            }
        }
    }

    // ---- epilogue: add masked mass exactly, normalize, write [B,S,D] ----
#pragma unroll
    for (int i = 0; i < 8; i++) {
        int qg = qb * 128 + ty * 8 + i;
        float e   = __expf(1e-9f - mi[i]);
        float cnt = (float)(cfg::S - 1 - qg);
        float denom = li[i] + cnt * e;
        float sv0 = 0.f, sv1 = 0.f, sv2 = 0.f, sv3 = 0.f;
        if (qg + 1 < cfg::S) {
            const float* svp = g_SV + base + (size_t)(qg + 1) * cfg::HD + tx * 4;
            sv0 = svp[0]; sv1 = svp[1]; sv2 = svp[2]; sv3 = svp[3];
        }
        float inv = 1.0f / denom;
        float4 r;
        r.x = (o[i][0] + e * sv0) * inv;
        r.y = (o[i][1] + e * sv1) * inv;
        r.z = (o[i][2] + e * sv2) * inv;
        r.w = (o[i][3] + e * sv3) * inv;
        *(float4*)(g_A + ((size_t)(b * cfg::S + qg)) * cfg::D + h * cfg::HD + tx * 4) = r;
    }
}

// ============================================================================
// launcher
// ============================================================================
extern "C" void kernel_launch(void* const* d_in, const int* in_sizes, int n_in,
                              void* d_out, int out_size)
{
    (void)in_sizes; (void)n_in; (void)out_size;
    const float* x      = (const float*)d_in[0];
    const float* w_attn = (const float*)d_in[1];
    const float* b_attn = (const float*)d_in[2];
    const float* w_proj = (const float*)d_in[3];
    const float* b_proj = (const float*)d_in[4];
    float* out = (float*)d_out;

    float *p_qkv = nullptr, *p_a = nullptr;
    cudaGetSymbolAddress((void**)&p_qkv, g_QKV);
    cudaGetSymbolAddress((void**)&p_a,   g_A);

    cudaFuncSetAttribute(attn_kernel, cudaFuncAttributeMaxDynamicSharedMemorySize,
                         ATTN_SMEM_BYTES);

    // 1) qkv = x @ w_attn + b_attn
    sgemm_bias_kernel<<<dim3(cfg::NQKV / 128, cfg::MTOK / 128), 256>>>(
        x, w_attn, b_attn, p_qkv, cfg::MTOK, cfg::NQKV, cfg::D);

    // 2) scatter into per-head Q/K/V
    scatter_qkv_kernel<<<(cfg::BH * cfg::S * cfg::HD + 255) / 256, 256>>>();

    // 3) V suffix sums (for exact masked-softmax mass)
    suffix_pass1<<<cfg::BH * 4, 64>>>();
    suffix_pass2<<<cfg::BH * 3, 64>>>();

    // 4) flash attention with exact reference mask semantics
    attn_kernel<<<dim3(cfg::S / 128, cfg::BH), 256, ATTN_SMEM_BYTES>>>();

    // 5) out = A @ w_proj + b_proj
    sgemm_bias_kernel<<<dim3(cfg::D / 128, cfg::MTOK / 128), 256>>>(
        p_a, w_proj, b_proj, out, cfg::MTOK, cfg::D, cfg::D);
}

// round 2
// speedup vs baseline: 1.2831x; 1.2831x over previous
#include <cuda_runtime.h>
#include <cstdint>

// Problem constants (fixed shapes per reference)
namespace cfg {
constexpr int B  = 4;
constexpr int S  = 2048;
constexpr int D  = 768;
constexpr int H  = 12;
constexpr int HD = 64;            // head dim
constexpr int MTOK = B * S;       // 8192 token rows
constexpr int NQKV = 3 * D;       // 2304
constexpr int BH   = B * H;       // 48
}

// -------- scratch (static device globals; no runtime allocation) --------
__device__ float g_Q  [(size_t)cfg::BH * cfg::S * cfg::HD];     // 25.2 MB each
__device__ float g_K  [(size_t)cfg::BH * cfg::S * cfg::HD];
__device__ float g_V  [(size_t)cfg::BH * cfg::S * cfg::HD];
__device__ float g_SV [(size_t)cfg::BH * cfg::S * cfg::HD];     // V suffix sums
__device__ float g_A  [(size_t)cfg::MTOK * cfg::D];             // attention output

// ============================================================================
// SGEMM: C[M,N] = A[M,K] @ B[K,N] + bias[N]
// 128x128 tile, BK=8 double-buffered (1 sync/iter), 256 threads,
// 8x8/thread split-tile, float4 LDS fragments.
// SCATTER=true: N==2304 QKV output scattered directly into g_Q/g_K/g_V
// ============================================================================
template<bool SCATTER>
__global__ void __launch_bounds__(256) sgemm_bias_kernel(
    const float* __restrict__ A, const float* __restrict__ Bm,
    const float* __restrict__ bias, float* __restrict__ C,
    int M, int N, int K)
{
    __shared__ float As[2][8][128];   // As[buf][k][m]
    __shared__ float Bs[2][8][128];   // Bs[buf][k][n]
    const int tid = threadIdx.x;
    const int tx  = tid & 15;      // 16 col-groups
    const int ty  = tid >> 4;      // 16 row-groups
    const int m0  = blockIdx.y * 128;
    const int n0  = blockIdx.x * 128;

    // A loader: thread -> (row lm, 4 k's)
    const int lm  = tid >> 1;            // 0..127
    const int lk  = (tid & 1) * 4;       // 0 or 4
    // B loader: thread -> (k row lbk, 4 n's)
    const int lbk = tid >> 5;            // 0..7
    const int lbn = (tid & 31) * 4;      // 0..124

    float acc[8][8];
#pragma unroll
    for (int i = 0; i < 8; i++)
#pragma unroll
        for (int j = 0; j < 8; j++) acc[i][j] = 0.f;

    // prologue: fill buffer 0
    float4 av = *(const float4*)(A  + (size_t)(m0 + lm) * K + lk);
    float4 bv = *(const float4*)(Bm + (size_t)lbk * N + (n0 + lbn));
    As[0][lk + 0][lm] = av.x;
    As[0][lk + 1][lm] = av.y;
    As[0][lk + 2][lm] = av.z;
    As[0][lk + 3][lm] = av.w;
    *(float4*)&Bs[0][lbk][lbn] = bv;
    __syncthreads();

    int buf = 0;
    for (int k0 = 0; k0 < K; k0 += 8) {
        const bool more = (k0 + 8) < K;
        if (more) {
            av = *(const float4*)(A  + (size_t)(m0 + lm) * K + (k0 + 8 + lk));
            bv = *(const float4*)(Bm + (size_t)(k0 + 8 + lbk) * N + (n0 + lbn));
        }
#pragma unroll
        for (int kk = 0; kk < 8; kk++) {
            float4 a0 = *(const float4*)&As[buf][kk][ty * 4];
            float4 a1 = *(const float4*)&As[buf][kk][64 + ty * 4];
            float4 b0 = *(const float4*)&Bs[buf][kk][tx * 4];
            float4 b1 = *(const float4*)&Bs[buf][kk][64 + tx * 4];
            float a[8] = {a0.x, a0.y, a0.z, a0.w, a1.x, a1.y, a1.z, a1.w};
            float b[8] = {b0.x, b0.y, b0.z, b0.w, b1.x, b1.y, b1.z, b1.w};
#pragma unroll
            for (int i = 0; i < 8; i++)
#pragma unroll
                for (int j = 0; j < 8; j++) acc[i][j] += a[i] * b[j];
        }
        if (more) {
            const int nb = buf ^ 1;
            As[nb][lk + 0][lm] = av.x;
            As[nb][lk + 1][lm] = av.y;
            As[nb][lk + 2][lm] = av.z;
            As[nb][lk + 3][lm] = av.w;
            *(float4*)&Bs[nb][lbk][lbn] = bv;
        }
        __syncthreads();
        buf ^= 1;
    }

#pragma unroll
    for (int i = 0; i < 8; i++) {
        int m = m0 + ((i < 4) ? (ty * 4 + i) : (64 + ty * 4 + (i - 4)));
#pragma unroll
        for (int jh = 0; jh < 2; jh++) {
            int n = n0 + jh * 64 + tx * 4;
            float4 r;
            r.x = acc[i][jh * 4 + 0] + bias[n + 0];
            r.y = acc[i][jh * 4 + 1] + bias[n + 1];
            r.z = acc[i][jh * 4 + 2] + bias[n + 2];
            r.w = acc[i][jh * 4 + 3] + bias[n + 3];
            if (!SCATTER) {
                *(float4*)(C + (size_t)m * N + n) = r;
            } else {
                // QKV scatter: n in [0,2304) -> (part, head, chan)
                int part = n / cfg::D;            // 0=q 1=k 2=v
                int dn   = n - part * cfg::D;
                int h    = dn >> 6;
                int c    = dn & 63;
                int b    = m >> 11;               // S = 2048
                int s    = m & 2047;
                float* dst = (part == 0) ? g_Q : (part == 1) ? g_K : g_V;
                size_t off = ((size_t)(b * cfg::H + h) * cfg::S + s) * cfg::HD + c;
                *(float4*)(dst + off) = r;
            }
        }
    }
}

// ============================================================================
// V suffix sums (fused single kernel): SV[bh][s][d] = sum_{k>=s} V[bh][k][d]
// grid=48 (one bh), block=512 = 16 float4 d-lanes x 32 segments of 64 rows.
// Pass A: per-segment reverse scan; Pass B: add later-segment totals (L2-hot).
// ============================================================================
__global__ void __launch_bounds__(512) suffix_kernel()
{
    __shared__ float tot[32][64];
    const int bh    = blockIdx.x;
    const int t     = threadIdx.x;
    const int lane4 = t & 15;         // float4 lane within d (16 lanes x 4 = 64)
    const int seg   = t >> 4;         // 0..31
    const size_t base = (size_t)bh * cfg::S * cfg::HD;
    const float4* Vp = (const float4*)(g_V + base);
    float4* SVp = (float4*)(g_SV + base);

    const int r0 = seg * 64;
    float4 acc = make_float4(0.f, 0.f, 0.f, 0.f);
    for (int r = r0 + 63; r >= r0; r--) {
        float4 v = Vp[(size_t)r * 16 + lane4];
        acc.x += v.x; acc.y += v.y; acc.z += v.z; acc.w += v.w;
        SVp[(size_t)r * 16 + lane4] = acc;
    }
    *(float4*)&tot[seg][lane4 * 4] = acc;
    __syncthreads();

    float4 off = make_float4(0.f, 0.f, 0.f, 0.f);
    for (int s2 = seg + 1; s2 < 32; s2++) {
        float4 tv = *(const float4*)&tot[s2][lane4 * 4];
        off.x += tv.x; off.y += tv.y; off.z += tv.z; off.w += tv.w;
    }
    if (seg < 31) {
        for (int r = r0; r < r0 + 64; r++) {
            float4 v = SVp[(size_t)r * 16 + lane4];
            v.x += off.x; v.y += off.y; v.z += off.z; v.w += off.w;
            SVp[(size_t)r * 16 + lane4] = v;
        }
    }
}

// ============================================================================
// Flash attention with EXACT reference mask semantics.
// Reference: w = s*mask + 1e-9*(1-mask); softmax over ALL S entries. We GEMM
// only the causal lower triangle; masked mass added analytically via V suffix
// sums: out = (o + e*SV[q+1]) / (l + cnt*e), e = exp(1e-9 - m). Identical by
// softmax shift-invariance.
// ============================================================================
constexpr int ATTN_SMEM_FLOATS = 128 * 65 + 64 * 65 + 64 * 65 + 128 * 65;  // 24960
constexpr int ATTN_SMEM_BYTES  = ATTN_SMEM_FLOATS * 4;                      // 99840

__global__ void __launch_bounds__(256) attn_kernel()
{
    extern __shared__ float smf[];
    float* Qs = smf;                  // [128][65]
    float* Ks = Qs + 128 * 65;        // [64][65]
    float* Vs = Ks + 64 * 65;         // [64][65]
    float* Ps = Vs + 64 * 65;         // [128][65]

    const int qb = (int)gridDim.x - 1 - (int)blockIdx.x;  // heavy tiles first
    const int bh = blockIdx.y;        // 0..47
    const int b  = bh / cfg::H;
    const int h  = bh % cfg::H;
    const size_t base = (size_t)bh * cfg::S * cfg::HD;

    const int tid = threadIdx.x;
    const int tx  = tid & 15;         // key/d-col group
    const int ty  = tid >> 4;         // row group (8 rows each)

    // load Q tile (128 x 64)
    for (int i = tid; i < 128 * 16; i += 256) {
        int r  = i >> 4;
        int c4 = (i & 15) << 2;
        float4 t = *(const float4*)(g_Q + base + (size_t)(qb * 128 + r) * cfg::HD + c4);
        float* q = &Qs[r * 65 + c4];
        q[0] = t.x; q[1] = t.y; q[2] = t.z; q[3] = t.w;
    }

    float o[8][4];
    float mi[8], li[8];
#pragma unroll
    for (int i = 0; i < 8; i++) {
        mi[i] = -1e30f;
        li[i] = 0.f;
#pragma unroll
        for (int j = 0; j < 4; j++) o[i][j] = 0.f;
    }

    const int nkb = 2 * qb + 2;       // keys up to (qb+1)*128
    for (int kb = 0; kb < nkb; kb++) {
        __syncthreads();
        for (int i = tid; i < 64 * 16; i += 256) {
            int r  = i >> 4;
            int c4 = (i & 15) << 2;
            float4 tk = *(const float4*)(g_K + base + (size_t)(kb * 64 + r) * cfg::HD + c4);
            float4 tv = *(const float4*)(g_V + base + (size_t)(kb * 64 + r) * cfg::HD + c4);
            float* kd = &Ks[r * 65 + c4];
            kd[0] = tk.x; kd[1] = tk.y; kd[2] = tk.z; kd[3] = tk.w;
            float* vd = &Vs[r * 65 + c4];
            vd[0] = tv.x; vd[1] = tv.y; vd[2] = tv.z; vd[3] = tv.w;
        }
        __syncthreads();

        // ---- S = Q K^T ----
        float s[8][4];
#pragma unroll
        for (int i = 0; i < 8; i++)
#pragma unroll
            for (int j = 0; j < 4; j++) s[i][j] = 0.f;

#pragma unroll 4
        for (int d = 0; d < 64; d++) {
            float bk[4];
#pragma unroll
            for (int j = 0; j < 4; j++) bk[j] = Ks[(tx * 4 + j) * 65 + d];
#pragma unroll
            for (int i = 0; i < 8; i++) {
                float aq = Qs[(ty * 8 + i) * 65 + d];
#pragma unroll
                for (int j = 0; j < 4; j++) s[i][j] += aq * bk[j];
            }
        }

        // ---- causal exclusion ----
        if (kb >= 2 * qb) {
#pragma unroll
            for (int i = 0; i < 8; i++) {
                int qg = qb * 128 + ty * 8 + i;
#pragma unroll
                for (int j = 0; j < 4; j++) {
                    int kg = kb * 64 + tx * 4 + j;
                    if (kg > qg) s[i][j] = -1e30f;
                }
            }
        }

        // ---- online softmax (16 lanes/row share stats) ----
#pragma unroll
        for (int i = 0; i < 8; i++) {
            float mloc = fmaxf(fmaxf(s[i][0], s[i][1]), fmaxf(s[i][2], s[i][3]));
            mloc = fmaxf(mloc, __shfl_xor_sync(0xffffffffu, mloc, 8, 16));
            mloc = fmaxf(mloc, __shfl_xor_sync(0xffffffffu, mloc, 4, 16));
            mloc = fmaxf(mloc, __shfl_xor_sync(0xffffffffu, mloc, 2, 16));
            mloc = fmaxf(mloc, __shfl_xor_sync(0xffffffffu, mloc, 1, 16));
            float mnew = fmaxf(mi[i], mloc);
            float corr = __expf(mi[i] - mnew);
            float ps = 0.f;
#pragma unroll
            for (int j = 0; j < 4; j++) {
                float p = __expf(s[i][j] - mnew);
                Ps[(ty * 8 + i) * 65 + tx * 4 + j] = p;
                ps += p;
            }
            ps += __shfl_xor_sync(0xffffffffu, ps, 8, 16);
            ps += __shfl_xor_sync(0xffffffffu, ps, 4, 16);
            ps += __shfl_xor_sync(0xffffffffu, ps, 2, 16);
            ps += __shfl_xor_sync(0xffffffffu, ps, 1, 16);
            li[i] = li[i] * corr + ps;
            mi[i] = mnew;
            o[i][0] *= corr; o[i][1] *= corr; o[i][2] *= corr; o[i][3] *= corr;
        }
        __syncwarp();

        // ---- O += P V ----
#pragma unroll 4
        for (int c = 0; c < 64; c++) {
            float vv[4];
#pragma unroll
            for (int j = 0; j < 4; j++) vv[j] = Vs[c * 65 + tx * 4 + j];
#pragma unroll
            for (int i = 0; i < 8; i++) {
                float p = Ps[(ty * 8 + i) * 65 + c];
#pragma unroll
                for (int j = 0; j < 4; j++) o[i][j] += p * vv[j];
            }
        }
    }

    // ---- epilogue: exact masked mass, normalize, write [B,S,D] ----
#pragma unroll
    for (int i = 0; i < 8; i++) {
        int qg = qb * 128 + ty * 8 + i;
        float e   = __expf(1e-9f - mi[i]);
        float cnt = (float)(cfg::S - 1 - qg);
        float denom = li[i] + cnt * e;
        float sv0 = 0.f, sv1 = 0.f, sv2 = 0.f, sv3 = 0.f;
        if (qg + 1 < cfg::S) {
            const float* svp = g_SV + base + (size_t)(qg + 1) * cfg::HD + tx * 4;
            sv0 = svp[0]; sv1 = svp[1]; sv2 = svp[2]; sv3 = svp[3];
        }
        float inv = 1.0f / denom;
        float4 r;
        r.x = (o[i][0] + e * sv0) * inv;
        r.y = (o[i][1] + e * sv1) * inv;
        r.z = (o[i][2] + e * sv2) * inv;
        r.w = (o[i][3] + e * sv3) * inv;
        *(float4*)(g_A + ((size_t)(b * cfg::S + qg)) * cfg::D + h * cfg::HD + tx * 4) = r;
    }
}

// ============================================================================
// launcher
// ============================================================================
extern "C" void kernel_launch(void* const* d_in, const int* in_sizes, int n_in,
                              void* d_out, int out_size)
{
    (void)in_sizes; (void)n_in; (void)out_size;
    const float* x      = (const float*)d_in[0];
    const float* w_attn = (const float*)d_in[1];
    const float* b_attn = (const float*)d_in[2];
    const float* w_proj = (const float*)d_in[3];
    const float* b_proj = (const float*)d_in[4];
    float* out = (float*)d_out;

    float* p_a = nullptr;
    cudaGetSymbolAddress((void**)&p_a, g_A);

    cudaFuncSetAttribute(attn_kernel, cudaFuncAttributeMaxDynamicSharedMemorySize,
                         ATTN_SMEM_BYTES);

    // 1) qkv = x @ w_attn + b_attn, scattered directly into g_Q/g_K/g_V
    sgemm_bias_kernel<true><<<dim3(cfg::NQKV / 128, cfg::MTOK / 128), 256>>>(
        x, w_attn, b_attn, nullptr, cfg::MTOK, cfg::NQKV, cfg::D);

    // 2) V suffix sums (exact masked-softmax mass), fused single kernel
    suffix_kernel<<<cfg::BH, 512>>>();

    // 3) flash attention with exact reference mask semantics
    attn_kernel<<<dim3(cfg::S / 128, cfg::BH), 256, ATTN_SMEM_BYTES>>>();

    // 4) out = A @ w_proj + b_proj
    sgemm_bias_kernel<false><<<dim3(cfg::D / 128, cfg::MTOK / 128), 256>>>(
        p_a, w_proj, b_proj, out, cfg::MTOK, cfg::D, cfg::D);
}

// round 4
// speedup vs baseline: 1.6289x; 1.2695x over previous
#include <cuda_runtime.h>
#include <cstdint>

// ============================================================================
// Arch-feature gate: tcgen05 arch-specific instructions (ld/st/wait/fence/
// dealloc/relinquish) only exist on sm_10Xa targets. A non-'a' compilation
// pass (e.g. compute_103 -> sm_103) must compile the fp32 fallback instead.
// ============================================================================
#if defined(__CUDA_ARCH_FEAT_SM103_ALL) || defined(__CUDA_ARCH_FEAT_SM100_ALL) || \
    defined(__CUDA_ARCH_FEAT_SM101_ALL)
#define TC_OK 1
#else
#define TC_OK 0
#endif

// ============================================================================
// Problem constants
// ============================================================================
namespace cfg {
constexpr int B  = 4;
constexpr int S  = 2048;
constexpr int D  = 768;
constexpr int H  = 12;
constexpr int HD = 64;
constexpr int MTOK = B * S;       // 8192
constexpr int NQKV = 3 * D;       // 2304
constexpr int BH   = B * H;       // 48
}

// -------- scratch (static device globals) --------
__device__ float g_Q  [(size_t)cfg::BH * cfg::S * cfg::HD];
__device__ float g_K  [(size_t)cfg::BH * cfg::S * cfg::HD];
__device__ float g_V  [(size_t)cfg::BH * cfg::S * cfg::HD];
__device__ float g_SV [(size_t)cfg::BH * cfg::S * cfg::HD];
__device__ float g_A  [(size_t)cfg::MTOK * cfg::D];
__device__ float g_WTa[(size_t)cfg::NQKV * cfg::D];   // w_attn^T [2304][768]
__device__ float g_WTp[(size_t)cfg::D * cfg::D];      // w_proj^T [768][768]

// ============================================================================
// PTX helpers
// ============================================================================
__device__ __forceinline__ uint32_t smem_to_u32(const void* p) {
    uint32_t a;
    asm("{ .reg .u64 t; cvta.to.shared.u64 t, %1; cvt.u32.u64 %0, t; }"
        : "=r"(a) : "l"(p));
    return a;
}

#if TC_OK
__device__ __forceinline__ uint32_t elect_one_pred() {
    uint32_t pred;
    asm volatile(
        "{\n\t.reg .pred p;\n\telect.sync _|p, 0xFFFFFFFF;\n\t"
        "selp.b32 %0, 1, 0, p;\n\t}"
        : "=r"(pred));
    return pred;
}

#define TCGEN05_ALLOC(smem_result_addr, nCols) \
    asm volatile("tcgen05.alloc.cta_group::1.sync.aligned.shared::cta.b32 [%0], %1;" \
                 :: "r"((uint32_t)(smem_result_addr)), "r"((uint32_t)(nCols)) : "memory")
#define TCGEN05_DEALLOC(tmem_addr, nCols) \
    asm volatile("tcgen05.dealloc.cta_group::1.sync.aligned.b32 %0, %1;" \
                 :: "r"(tmem_addr), "r"((uint32_t)(nCols)))
#define TCGEN05_RELINQUISH() \
    asm volatile("tcgen05.relinquish_alloc_permit.cta_group::1.sync.aligned;")
#define TCGEN05_COMMIT(mbar) \
    asm volatile("tcgen05.commit.cta_group::1.mbarrier::arrive::one.shared::cluster.b64 [%0];" \
                 :: "r"((uint32_t)(mbar)) : "memory")
#define TCGEN05_WAIT_LD() asm volatile("tcgen05.wait::ld.sync.aligned;" ::: "memory")
#define TCGEN05_FENCE_AFTER()  asm volatile("tcgen05.fence::after_thread_sync;" ::: "memory")
#define TCGEN05_FENCE_BEFORE() asm volatile("tcgen05.fence::before_thread_sync;" ::: "memory")
#define FENCE_PROXY_ASYNC() asm volatile("fence.proxy.async.shared::cta;" ::: "memory")

#define MBARRIER_INIT(mbar, count) \
    asm volatile("mbarrier.init.shared.b64 [%0], %1;" \
                 :: "r"((uint32_t)(mbar)), "r"((uint32_t)(count)) : "memory")
#define MBARRIER_INVAL(mbar) \
    asm volatile("mbarrier.inval.shared.b64 [%0];" :: "r"((uint32_t)(mbar)) : "memory")

#define MBARRIER_WAIT_PARITY(mbar_addr, phase_parity) do { \
    uint32_t _mbar = (uint32_t)(mbar_addr); \
    uint32_t _parity = (uint32_t)(phase_parity); \
    uint32_t _done; \
    asm volatile( \
        "{\n\t.reg .pred p;\n\t" \
        "mbarrier.try_wait.parity.acquire.cta.shared::cta.b64 p, [%1], %2;\n\t" \
        "selp.b32 %0, 1, 0, p;\n\t}" \
        : "=r"(_done) : "r"(_mbar), "r"(_parity) : "memory"); \
    if (!_done) { \
        asm volatile( \
            "{\n\t.reg .pred P1;\n\t" \
            "WAIT_LOOP_%=:\n\t" \
            "mbarrier.try_wait.parity.acquire.cta.shared::cta.b64 P1, [%0], %1, 0x989680;\n\t" \
            "@P1 bra.uni WAIT_DONE_%=;\n\t" \
            "bra.uni WAIT_LOOP_%=;\n\t" \
            "WAIT_DONE_%=:\n\t}" \
            :: "r"(_mbar), "r"(_parity) : "memory"); \
    } \
} while(0)

#define TCGEN05_LD_32X32B_X32(r, tmem_addr) \
    asm volatile( \
        "tcgen05.ld.sync.aligned.32x32b.x32.b32 " \
        "{%0, %1, %2, %3, %4, %5, %6, %7, " \
        " %8, %9, %10, %11, %12, %13, %14, %15, " \
        " %16, %17, %18, %19, %20, %21, %22, %23, " \
        " %24, %25, %26, %27, %28, %29, %30, %31}, [%32];" \
        : "=r"((r)[0]),  "=r"((r)[1]),  "=r"((r)[2]),  "=r"((r)[3]), \
          "=r"((r)[4]),  "=r"((r)[5]),  "=r"((r)[6]),  "=r"((r)[7]), \
          "=r"((r)[8]),  "=r"((r)[9]),  "=r"((r)[10]), "=r"((r)[11]), \
          "=r"((r)[12]), "=r"((r)[13]), "=r"((r)[14]), "=r"((r)[15]), \
          "=r"((r)[16]), "=r"((r)[17]), "=r"((r)[18]), "=r"((r)[19]), \
          "=r"((r)[20]), "=r"((r)[21]), "=r"((r)[22]), "=r"((r)[23]), \
          "=r"((r)[24]), "=r"((r)[25]), "=r"((r)[26]), "=r"((r)[27]), \
          "=r"((r)[28]), "=r"((r)[29]), "=r"((r)[30]), "=r"((r)[31]) \
        : "r"(tmem_addr))

// SW128 smem descriptor: layout=2(SW128), version=1, SBO=64 (1024B), LBO=1 (16B)
static constexpr uint64_t SMEM_DESC_BASE_SW128 =
    (uint64_t(2)  << 61) | (uint64_t(1) << 46) | (uint64_t(64) << 32) | (uint64_t(1) << 16);
#define MAKE_SMEM_DESC(base_addr) \
    (SMEM_DESC_BASE_SW128 | ((uint64_t)((base_addr) >> 4) & 0x3FFF))

// tf32 SS MMA, cta_group::1
__device__ __forceinline__ void mma_tf32_ss(uint32_t d, uint64_t ad, uint64_t bd,
                                            uint32_t idesc, bool acc) {
    uint32_t en = acc ? 1u : 0u;
    asm volatile(
        "{\n\t.reg .pred p;\n\tsetp.ne.u32 p, %5, 0;\n\t"
        "tcgen05.mma.cta_group::1.kind::tf32 [%0], %1, %2, %3, {%4, %4, %4, %4}, p;\n\t}"
        :: "r"(d), "l"(ad), "l"(bd), "r"(idesc), "r"(0u), "r"(en)
        : "memory");
}

// idesc: c=F32(1@4), a=TF32(2@7), b=TF32(2@10), N=128(16@17), M=128(8@24)
static constexpr uint32_t IDESC_TF32_128x128 =
    (1u << 4) | (2u << 7) | (2u << 10) | ((128u / 8u) << 17) | ((128u / 16u) << 24);
#endif  // TC_OK

#define SMEM_SWIZZLE_128B(off) ((off) ^ (((off) >> 3) & 0x70))

// round-to-nearest tf32 (fp32 with low mantissa zeroed) — safe on any target
__device__ __forceinline__ float tf32_rna(float x) {
    uint32_t u;
    asm("cvt.rna.tf32.f32 %0, %1;" : "=r"(u) : "f"(x));
    return __uint_as_float(u);
}

// ============================================================================
// Weight transpose: out[C][R] = in[R][C]
// ============================================================================
__global__ void transpose_kernel(const float* __restrict__ in, float* __restrict__ out,
                                 int R, int C)
{
    __shared__ float t[32][33];
    int bx = blockIdx.x * 32;
    int by = blockIdx.y * 32;
    int x = bx + threadIdx.x;
#pragma unroll
    for (int j = 0; j < 32; j += 8)
        t[threadIdx.y + j][threadIdx.x] = in[(size_t)(by + threadIdx.y + j) * C + x];
    __syncthreads();
    int x2 = by + threadIdx.x;
#pragma unroll
    for (int j = 0; j < 32; j += 8)
        out[(size_t)(bx + threadIdx.y + j) * R + x2] = t[threadIdx.x][threadIdx.y + j];
}

// ============================================================================
// GEMM: C[M,N] = A[M,K] @ BT[N,K]^T + bias[N]
//   TC_OK=1: tcgen05 tf32 3x-split, 128x128 tile, BK=32, 2-stage pipeline
//   TC_OK=0: fp32 double-buffered SGEMM (round-2 algorithm), both operands
//            K-major (A and BT), 128x128 tile, BK=8
// SCATTER=true: QKV output (N=2304) scattered into per-head g_Q/g_K/g_V.
// ============================================================================
constexpr int GT_TILE_BYTES  = 128 * 32 * 4;
constexpr int GT_STAGE_BYTES = 4 * GT_TILE_BYTES;
constexpr int GT_SMEM_TILES0 = 1024;
constexpr int GT_SMEM_TOTAL  = GT_SMEM_TILES0 + 2 * GT_STAGE_BYTES;  // 132096
constexpr int GT_TMEM_COLS   = 128;

template<bool SCATTER>
__device__ __forceinline__ void gemm_epilogue_store(
    const float* __restrict__ buf, const float* __restrict__ bias,
    float* __restrict__ C, int m0, int n0, int N, int tid)
{
#pragma unroll
    for (int i = 0; i < 16; i++) {
        int g  = tid + i * 256;
        int r  = g >> 5;
        int c4 = (g & 31) * 4;
        const float* row = buf + (size_t)r * 132 + c4;
        int n = n0 + c4;
        float4 bv = *(const float4*)(bias + n);
        float4 v;
        v.x = row[0] + bv.x; v.y = row[1] + bv.y;
        v.z = row[2] + bv.z; v.w = row[3] + bv.w;
        int m = m0 + r;
        if (!SCATTER) {
            *(float4*)(C + (size_t)m * N + n) = v;
        } else {
            int part = n / cfg::D;
            int dn   = n - part * cfg::D;
            int h    = dn >> 6;
            int c    = dn & 63;
            int b_   = m >> 11;
            int s_   = m & 2047;
            float* dst = (part == 0) ? g_Q : (part == 1) ? g_K : g_V;
            *(float4*)(dst + ((size_t)(b_ * cfg::H + h) * cfg::S + s_) * cfg::HD + c) = v;
        }
    }
}

template<bool SCATTER>
__global__ void __launch_bounds__(256) gemm_tf32_kernel(
    const float* __restrict__ A, const float* __restrict__ BT,
    const float* __restrict__ bias, float* __restrict__ C,
    int M, int N, int K)
{
    extern __shared__ char smem[];
    const int tid = threadIdx.x;
    const int m0  = blockIdx.y * 128;
    const int n0  = blockIdx.x * 128;

#if TC_OK
    // ---------------- tcgen05 tf32 path ----------------
    const uint32_t smem_base = smem_to_u32(smem);
    const uint32_t mbar0 = smem_base + 16;
    const uint32_t mbar1 = smem_base + 24;
    const int wid = tid >> 5;
    const int lid = tid & 31;

    if (wid == 0) TCGEN05_ALLOC(smem_base, GT_TMEM_COLS);
    if (tid == 0) {
        MBARRIER_INIT(mbar0, 1);
        MBARRIER_INIT(mbar1, 1);
    }
    __syncthreads();
    uint32_t tmem;
    asm volatile("ld.shared.b32 %0, [%1];" : "=r"(tmem) : "r"(smem_base));

    const int T = K / 32;
    int ph0 = 0, ph1 = 0;

    for (int t = 0; t < T; t++) {
        const int s = t & 1;
        const uint32_t stage = smem_base + GT_SMEM_TILES0 + s * GT_STAGE_BYTES;
        const uint32_t Ah = stage;
        const uint32_t Al = stage + GT_TILE_BYTES;
        const uint32_t Bh = stage + 2 * GT_TILE_BYTES;
        const uint32_t Bl = stage + 3 * GT_TILE_BYTES;

        if (t >= 2) {
            if (s == 0) { MBARRIER_WAIT_PARITY(mbar0, ph0); ph0 ^= 1; }
            else        { MBARRIER_WAIT_PARITY(mbar1, ph1); ph1 ^= 1; }
        }

        const int k0 = t * 32;
#pragma unroll
        for (int i = 0; i < 4; i++) {
            int g  = tid + i * 256;
            int r  = g >> 3;
            int c4 = (g & 7) * 4;
            float4 v = *(const float4*)(A + (size_t)(m0 + r) * K + k0 + c4);
            float4 vh, vl;
            vh.x = tf32_rna(v.x); vl.x = tf32_rna(v.x - vh.x);
            vh.y = tf32_rna(v.y); vl.y = tf32_rna(v.y - vh.y);
            vh.z = tf32_rna(v.z); vl.z = tf32_rna(v.z - vh.z);
            vh.w = tf32_rna(v.w); vl.w = tf32_rna(v.w - vh.w);
            uint32_t off = SMEM_SWIZZLE_128B((uint32_t)(r * 128 + c4 * 4));
            *(float4*)(smem + (Ah - smem_base) + off) = vh;
            *(float4*)(smem + (Al - smem_base) + off) = vl;
        }
#pragma unroll
        for (int i = 0; i < 4; i++) {
            int g  = tid + i * 256;
            int r  = g >> 3;
            int c4 = (g & 7) * 4;
            float4 v = *(const float4*)(BT + (size_t)(n0 + r) * K + k0 + c4);
            float4 vh, vl;
            vh.x = tf32_rna(v.x); vl.x = tf32_rna(v.x - vh.x);
            vh.y = tf32_rna(v.y); vl.y = tf32_rna(v.y - vh.y);
            vh.z = tf32_rna(v.z); vl.z = tf32_rna(v.z - vh.z);
            vh.w = tf32_rna(v.w); vl.w = tf32_rna(v.w - vh.w);
            uint32_t off = SMEM_SWIZZLE_128B((uint32_t)(r * 128 + c4 * 4));
            *(float4*)(smem + (Bh - smem_base) + off) = vh;
            *(float4*)(smem + (Bl - smem_base) + off) = vl;
        }
        __syncthreads();

        if (wid == 0) {
            if (elect_one_pred()) {
                FENCE_PROXY_ASYNC();
                uint64_t dah = MAKE_SMEM_DESC(Ah);
                uint64_t dal = MAKE_SMEM_DESC(Al);
                uint64_t dbh = MAKE_SMEM_DESC(Bh);
                uint64_t dbl = MAKE_SMEM_DESC(Bl);
#pragma unroll
                for (int j = 0; j < 4; j++) {
                    uint64_t oj = (uint64_t)(j * 2);
                    mma_tf32_ss(tmem, dah + oj, dbh + oj, IDESC_TF32_128x128,
                                !(t == 0 && j == 0));
                    mma_tf32_ss(tmem, dal + oj, dbh + oj, IDESC_TF32_128x128, true);
                    mma_tf32_ss(tmem, dah + oj, dbl + oj, IDESC_TF32_128x128, true);
                }
                TCGEN05_COMMIT(s == 0 ? mbar0 : mbar1);
            }
        }
    }

    MBARRIER_WAIT_PARITY(mbar0, ph0);
    MBARRIER_WAIT_PARITY(mbar1, ph1);
    TCGEN05_FENCE_AFTER();

    float* buf = (float*)(smem + GT_SMEM_TILES0);   // [128][132]
    if (wid < 4) {
#pragma unroll
        for (int b = 0; b < 4; b++) {
            uint32_t regs[32];
            TCGEN05_LD_32X32B_X32(regs, tmem + b * 32);
            TCGEN05_WAIT_LD();
            float* row = buf + (size_t)(wid * 32 + lid) * 132 + b * 32;
#pragma unroll
            for (int c = 0; c < 32; c++) row[c] = __uint_as_float(regs[c]);
        }
        TCGEN05_FENCE_BEFORE();
    }
    __syncthreads();

    gemm_epilogue_store<SCATTER>(buf, bias, C, m0, n0, N, tid);

    __syncthreads();
    if (tid == 0) { MBARRIER_INVAL(mbar0); MBARRIER_INVAL(mbar1); }
    __syncthreads();
    if (wid == 0) {
        TCGEN05_RELINQUISH();
        TCGEN05_DEALLOC(tmem, GT_TMEM_COLS);
    }

#else
    // ---------------- fp32 fallback path (both operands K-major) ----------------
    float* As = (float*)smem;                 // [2][8][128]  As[buf][k][m]
    float* Bs = As + 2 * 8 * 128;             // [2][8][128]  Bs[buf][k][n]
    const int tx = tid & 15;
    const int ty = tid >> 4;
    const int lr = tid >> 1;                  // 0..127 (row within tile)
    const int lk = (tid & 1) * 4;             // 0 or 4

    float acc[8][8];
#pragma unroll
    for (int i = 0; i < 8; i++)
#pragma unroll
        for (int j = 0; j < 8; j++) acc[i][j] = 0.f;

    float4 av = *(const float4*)(A  + (size_t)(m0 + lr) * K + lk);
    float4 bv = *(const float4*)(BT + (size_t)(n0 + lr) * K + lk);
    As[(lk + 0) * 128 + lr] = av.x;
    As[(lk + 1) * 128 + lr] = av.y;
    As[(lk + 2) * 128 + lr] = av.z;
    As[(lk + 3) * 128 + lr] = av.w;
    Bs[(lk + 0) * 128 + lr] = bv.x;
    Bs[(lk + 1) * 128 + lr] = bv.y;
    Bs[(lk + 2) * 128 + lr] = bv.z;
    Bs[(lk + 3) * 128 + lr] = bv.w;
    __syncthreads();

    int buf = 0;
    for (int k0 = 0; k0 < K; k0 += 8) {
        const bool more = (k0 + 8) < K;
        if (more) {
            av = *(const float4*)(A  + (size_t)(m0 + lr) * K + (k0 + 8 + lk));
            bv = *(const float4*)(BT + (size_t)(n0 + lr) * K + (k0 + 8 + lk));
        }
        const float* Ab = As + buf * 8 * 128;
        const float* Bb = Bs + buf * 8 * 128;
#pragma unroll
        for (int kk = 0; kk < 8; kk++) {
            float a[8], b[8];
#pragma unroll
            for (int i = 0; i < 4; i++) {
                a[i]     = Ab[kk * 128 + ty * 4 + i];
                a[i + 4] = Ab[kk * 128 + 64 + ty * 4 + i];
                b[i]     = Bb[kk * 128 + tx * 4 + i];
                b[i + 4] = Bb[kk * 128 + 64 + tx * 4 + i];
            }
#pragma unroll
            for (int i = 0; i < 8; i++)
#pragma unroll
                for (int j = 0; j < 8; j++) acc[i][j] += a[i] * b[j];
        }
        if (more) {
            float* An = As + (buf ^ 1) * 8 * 128;
            float* Bn = Bs + (buf ^ 1) * 8 * 128;
            An[(lk + 0) * 128 + lr] = av.x;
            An[(lk + 1) * 128 + lr] = av.y;
            An[(lk + 2) * 128 + lr] = av.z;
            An[(lk + 3) * 128 + lr] = av.w;
            Bn[(lk + 0) * 128 + lr] = bv.x;
            Bn[(lk + 1) * 128 + lr] = bv.y;
            Bn[(lk + 2) * 128 + lr] = bv.z;
            Bn[(lk + 3) * 128 + lr] = bv.w;
        }
        __syncthreads();
        buf ^= 1;
    }

#pragma unroll
    for (int i = 0; i < 8; i++) {
        int m = m0 + ((i < 4) ? (ty * 4 + i) : (64 + ty * 4 + (i - 4)));
#pragma unroll
        for (int jh = 0; jh < 2; jh++) {
            int n = n0 + jh * 64 + tx * 4;
            float4 r;
            r.x = acc[i][jh * 4 + 0] + bias[n + 0];
            r.y = acc[i][jh * 4 + 1] + bias[n + 1];
            r.z = acc[i][jh * 4 + 2] + bias[n + 2];
            r.w = acc[i][jh * 4 + 3] + bias[n + 3];
            if (!SCATTER) {
                *(float4*)(C + (size_t)m * N + n) = r;
            } else {
                int part = n / cfg::D;
                int dn   = n - part * cfg::D;
                int h    = dn >> 6;
                int c    = dn & 63;
                int b_   = m >> 11;
                int s_   = m & 2047;
                float* dst = (part == 0) ? g_Q : (part == 1) ? g_K : g_V;
                *(float4*)(dst + ((size_t)(b_ * cfg::H + h) * cfg::S + s_) * cfg::HD + c) = r;
            }
        }
    }
#endif
}

// ============================================================================
// V suffix sums (exact masked-softmax mass)
// ============================================================================
__global__ void __launch_bounds__(512) suffix_kernel()
{
    __shared__ float tot[32][64];
    const int bh    = blockIdx.x;
    const int t     = threadIdx.x;
    const int lane4 = t & 15;
    const int seg   = t >> 4;
    const size_t base = (size_t)bh * cfg::S * cfg::HD;
    const float4* Vp = (const float4*)(g_V + base);
    float4* SVp = (float4*)(g_SV + base);

    const int r0 = seg * 64;
    float4 acc = make_float4(0.f, 0.f, 0.f, 0.f);
    for (int r = r0 + 63; r >= r0; r--) {
        float4 v = Vp[(size_t)r * 16 + lane4];
        acc.x += v.x; acc.y += v.y; acc.z += v.z; acc.w += v.w;
        SVp[(size_t)r * 16 + lane4] = acc;
    }
    *(float4*)&tot[seg][lane4 * 4] = acc;
    __syncthreads();

    float4 off = make_float4(0.f, 0.f, 0.f, 0.f);
    for (int s2 = seg + 1; s2 < 32; s2++) {
        float4 tv = *(const float4*)&tot[s2][lane4 * 4];
        off.x += tv.x; off.y += tv.y; off.z += tv.z; off.w += tv.w;
    }
    if (seg < 31) {
        for (int r = r0; r < r0 + 64; r++) {
            float4 v = SVp[(size_t)r * 16 + lane4];
            v.x += off.x; v.y += off.y; v.z += off.z; v.w += off.w;
            SVp[(size_t)r * 16 + lane4] = v;
        }
    }
}

// ============================================================================
// Flash attention, EXACT reference mask semantics (fp32 CUDA cores)
// ============================================================================
constexpr int ATTN_SMEM_FLOATS = 128 * 65 + 64 * 65 + 64 * 65 + 128 * 65;
constexpr int ATTN_SMEM_BYTES  = ATTN_SMEM_FLOATS * 4;

__global__ void __launch_bounds__(256) attn_kernel()
{
    extern __shared__ float smf[];
    float* Qs = smf;
    float* Ks = Qs + 128 * 65;
    float* Vs = Ks + 64 * 65;
    float* Ps = Vs + 64 * 65;

    const int qb = (int)gridDim.x - 1 - (int)blockIdx.x;
    const int bh = blockIdx.y;
    const int b  = bh / cfg::H;
    const int h  = bh % cfg::H;
    const size_t base = (size_t)bh * cfg::S * cfg::HD;

    const int tid = threadIdx.x;
    const int tx  = tid & 15;
    const int ty  = tid >> 4;

    for (int i = tid; i < 128 * 16; i += 256) {
        int r  = i >> 4;
        int c4 = (i & 15) << 2;
        float4 t = *(const float4*)(g_Q + base + (size_t)(qb * 128 + r) * cfg::HD + c4);
        float* q = &Qs[r * 65 + c4];
        q[0] = t.x; q[1] = t.y; q[2] = t.z; q[3] = t.w;
    }

    float o[8][4];
    float mi[8], li[8];
#pragma unroll
    for (int i = 0; i < 8; i++) {
        mi[i] = -1e30f; li[i] = 0.f;
#pragma unroll
        for (int j = 0; j < 4; j++) o[i][j] = 0.f;
    }

    const int nkb = 2 * qb + 2;
    for (int kb = 0; kb < nkb; kb++) {
        __syncthreads();
        for (int i = tid; i < 64 * 16; i += 256) {
            int r  = i >> 4;
            int c4 = (i & 15) << 2;
            float4 tk = *(const float4*)(g_K + base + (size_t)(kb * 64 + r) * cfg::HD + c4);
            float4 tv = *(const float4*)(g_V + base + (size_t)(kb * 64 + r) * cfg::HD + c4);
            float* kd = &Ks[r * 65 + c4];
            kd[0] = tk.x; kd[1] = tk.y; kd[2] = tk.z; kd[3] = tk.w;
            float* vd = &Vs[r * 65 + c4];
            vd[0] = tv.x; vd[1] = tv.y; vd[2] = tv.z; vd[3] = tv.w;
        }
        __syncthreads();

        float s[8][4];
#pragma unroll
        for (int i = 0; i < 8; i++)
#pragma unroll
            for (int j = 0; j < 4; j++) s[i][j] = 0.f;

#pragma unroll 4
        for (int d = 0; d < 64; d++) {
            float bk[4];
#pragma unroll
            for (int j = 0; j < 4; j++) bk[j] = Ks[(tx * 4 + j) * 65 + d];
#pragma unroll
            for (int i = 0; i < 8; i++) {
                float aq = Qs[(ty * 8 + i) * 65 + d];
#pragma unroll
                for (int j = 0; j < 4; j++) s[i][j] += aq * bk[j];
            }
        }

        if (kb >= 2 * qb) {
#pragma unroll
            for (int i = 0; i < 8; i++) {
                int qg = qb * 128 + ty * 8 + i;
#pragma unroll
                for (int j = 0; j < 4; j++) {
                    int kg = kb * 64 + tx * 4 + j;
                    if (kg > qg) s[i][j] = -1e30f;
                }
            }
        }

#pragma unroll
        for (int i = 0; i < 8; i++) {
            float mloc = fmaxf(fmaxf(s[i][0], s[i][1]), fmaxf(s[i][2], s[i][3]));
            mloc = fmaxf(mloc, __shfl_xor_sync(0xffffffffu, mloc, 8, 16));
            mloc = fmaxf(mloc, __shfl_xor_sync(0xffffffffu, mloc, 4, 16));
            mloc = fmaxf(mloc, __shfl_xor_sync(0xffffffffu, mloc, 2, 16));
            mloc = fmaxf(mloc, __shfl_xor_sync(0xffffffffu, mloc, 1, 16));
            float mnew = fmaxf(mi[i], mloc);
            float corr = __expf(mi[i] - mnew);
            float ps = 0.f;
#pragma unroll
            for (int j = 0; j < 4; j++) {
                float p = __expf(s[i][j] - mnew);
                Ps[(ty * 8 + i) * 65 + tx * 4 + j] = p;
                ps += p;
            }
            ps += __shfl_xor_sync(0xffffffffu, ps, 8, 16);
            ps += __shfl_xor_sync(0xffffffffu, ps, 4, 16);
            ps += __shfl_xor_sync(0xffffffffu, ps, 2, 16);
            ps += __shfl_xor_sync(0xffffffffu, ps, 1, 16);
            li[i] = li[i] * corr + ps;
            mi[i] = mnew;
            o[i][0] *= corr; o[i][1] *= corr; o[i][2] *= corr; o[i][3] *= corr;
        }
        __syncwarp();

#pragma unroll 4
        for (int c = 0; c < 64; c++) {
            float vv[4];
#pragma unroll
            for (int j = 0; j < 4; j++) vv[j] = Vs[c * 65 + tx * 4 + j];
#pragma unroll
            for (int i = 0; i < 8; i++) {
                float p = Ps[(ty * 8 + i) * 65 + c];
#pragma unroll
                for (int j = 0; j < 4; j++) o[i][j] += p * vv[j];
            }
        }
    }

#pragma unroll
    for (int i = 0; i < 8; i++) {
        int qg = qb * 128 + ty * 8 + i;
        float e   = __expf(1e-9f - mi[i]);
        float cnt = (float)(cfg::S - 1 - qg);
        float denom = li[i] + cnt * e;
        float sv0 = 0.f, sv1 = 0.f, sv2 = 0.f, sv3 = 0.f;
        if (qg + 1 < cfg::S) {
            const float* svp = g_SV + base + (size_t)(qg + 1) * cfg::HD + tx * 4;
            sv0 = svp[0]; sv1 = svp[1]; sv2 = svp[2]; sv3 = svp[3];
        }
        float inv = 1.0f / denom;
        float4 r;
        r.x = (o[i][0] + e * sv0) * inv;
        r.y = (o[i][1] + e * sv1) * inv;
        r.z = (o[i][2] + e * sv2) * inv;
        r.w = (o[i][3] + e * sv3) * inv;
        *(float4*)(g_A + ((size_t)(b * cfg::S + qg)) * cfg::D + h * cfg::HD + tx * 4) = r;
    }
}

// ============================================================================
// launcher
// ============================================================================
extern "C" void kernel_launch(void* const* d_in, const int* in_sizes, int n_in,
                              void* d_out, int out_size)
{
    (void)in_sizes; (void)n_in; (void)out_size;
    const float* x      = (const float*)d_in[0];
    const float* w_attn = (const float*)d_in[1];
    const float* b_attn = (const float*)d_in[2];
    const float* w_proj = (const float*)d_in[3];
    const float* b_proj = (const float*)d_in[4];
    float* out = (float*)d_out;

    float *p_a = nullptr, *p_wta = nullptr, *p_wtp = nullptr;
    cudaGetSymbolAddress((void**)&p_a,   g_A);
    cudaGetSymbolAddress((void**)&p_wta, g_WTa);
    cudaGetSymbolAddress((void**)&p_wtp, g_WTp);

    cudaFuncSetAttribute(attn_kernel, cudaFuncAttributeMaxDynamicSharedMemorySize,
                         ATTN_SMEM_BYTES);
    cudaFuncSetAttribute(gemm_tf32_kernel<true>,
                         cudaFuncAttributeMaxDynamicSharedMemorySize, GT_SMEM_TOTAL);
    cudaFuncSetAttribute(gemm_tf32_kernel<false>,
                         cudaFuncAttributeMaxDynamicSharedMemorySize, GT_SMEM_TOTAL);

    // 0) weight transposes (BT layout: [N][K], K-major)
    transpose_kernel<<<dim3(cfg::NQKV / 32, cfg::D / 32), dim3(32, 8)>>>(
        w_attn, p_wta, cfg::D, cfg::NQKV);
    transpose_kernel<<<dim3(cfg::D / 32, cfg::D / 32), dim3(32, 8)>>>(
        w_proj, p_wtp, cfg::D, cfg::D);

    // 1) qkv = x @ w_attn + b_attn, scattered into g_Q/g_K/g_V
    gemm_tf32_kernel<true><<<dim3(cfg::NQKV / 128, cfg::MTOK / 128), 256, GT_SMEM_TOTAL>>>(
        x, p_wta, b_attn, nullptr, cfg::MTOK, cfg::NQKV, cfg::D);

    // 2) V suffix sums
    suffix_kernel<<<cfg::BH, 512>>>();

    // 3) flash attention (exact mask semantics)
    attn_kernel<<<dim3(cfg::S / 128, cfg::BH), 256, ATTN_SMEM_BYTES>>>();

    // 4) out = A @ w_proj + b_proj
    gemm_tf32_kernel<false><<<dim3(cfg::D / 128, cfg::MTOK / 128), 256, GT_SMEM_TOTAL>>>(
        p_a, p_wtp, b_proj, out, cfg::MTOK, cfg::D, cfg::D);
}

// round 5
// speedup vs baseline: 2.5683x; 1.5766x over previous
#include <cuda_runtime.h>
#include <cstdint>

// ============================================================================
// Arch-feature gate: arch-specific tcgen05 instructions only exist on sm_10Xa
// targets. The non-'a' compilation pass compiles fp32 fallbacks instead
// (never executed on GB300 — the sm_103a cubin is loaded).
// ============================================================================
#if defined(__CUDA_ARCH_FEAT_SM103_ALL) || defined(__CUDA_ARCH_FEAT_SM100_ALL) || \
    defined(__CUDA_ARCH_FEAT_SM101_ALL)
#define TC_OK 1
#else
#define TC_OK 0
#endif

// ============================================================================
// Problem constants
// ============================================================================
namespace cfg {
constexpr int B  = 4;
constexpr int S  = 2048;
constexpr int D  = 768;
constexpr int H  = 12;
constexpr int HD = 64;
constexpr int MTOK = B * S;       // 8192
constexpr int NQKV = 3 * D;       // 2304
constexpr int BH   = B * H;       // 48
}

// -------- scratch (static device globals) --------
__device__ float g_Q  [(size_t)cfg::BH * cfg::S * cfg::HD];
__device__ float g_K  [(size_t)cfg::BH * cfg::S * cfg::HD];
__device__ float g_V  [(size_t)cfg::BH * cfg::S * cfg::HD];
__device__ float g_SV [(size_t)cfg::BH * cfg::S * cfg::HD];
__device__ float g_A  [(size_t)cfg::MTOK * cfg::D];
__device__ float g_WTa[(size_t)cfg::NQKV * cfg::D];   // w_attn^T
__device__ float g_WTp[(size_t)cfg::D * cfg::D];      // w_proj^T

// ============================================================================
// PTX helpers
// ============================================================================
__device__ __forceinline__ uint32_t smem_to_u32(const void* p) {
    uint32_t a;
    asm("{ .reg .u64 t; cvta.to.shared.u64 t, %1; cvt.u32.u64 %0, t; }"
        : "=r"(a) : "l"(p));
    return a;
}

#if TC_OK
__device__ __forceinline__ uint32_t elect_one_pred() {
    uint32_t pred;
    asm volatile(
        "{\n\t.reg .pred p;\n\telect.sync _|p, 0xFFFFFFFF;\n\t"
        "selp.b32 %0, 1, 0, p;\n\t}"
        : "=r"(pred));
    return pred;
}

#define TCGEN05_ALLOC(smem_result_addr, nCols) \
    asm volatile("tcgen05.alloc.cta_group::1.sync.aligned.shared::cta.b32 [%0], %1;" \
                 :: "r"((uint32_t)(smem_result_addr)), "r"((uint32_t)(nCols)) : "memory")
#define TCGEN05_DEALLOC(tmem_addr, nCols) \
    asm volatile("tcgen05.dealloc.cta_group::1.sync.aligned.b32 %0, %1;" \
                 :: "r"(tmem_addr), "r"((uint32_t)(nCols)))
#define TCGEN05_RELINQUISH() \
    asm volatile("tcgen05.relinquish_alloc_permit.cta_group::1.sync.aligned;")
#define TCGEN05_COMMIT(mbar) \
    asm volatile("tcgen05.commit.cta_group::1.mbarrier::arrive::one.shared::cluster.b64 [%0];" \
                 :: "r"((uint32_t)(mbar)) : "memory")
#define TCGEN05_WAIT_LD() asm volatile("tcgen05.wait::ld.sync.aligned;" ::: "memory")
#define TCGEN05_WAIT_ST() asm volatile("tcgen05.wait::st.sync.aligned;" ::: "memory")
#define TCGEN05_FENCE_AFTER()  asm volatile("tcgen05.fence::after_thread_sync;" ::: "memory")
#define TCGEN05_FENCE_BEFORE() asm volatile("tcgen05.fence::before_thread_sync;" ::: "memory")
#define FENCE_PROXY_ASYNC() asm volatile("fence.proxy.async.shared::cta;" ::: "memory")

#define MBARRIER_INIT(mbar, count) \
    asm volatile("mbarrier.init.shared.b64 [%0], %1;" \
                 :: "r"((uint32_t)(mbar)), "r"((uint32_t)(count)) : "memory")
#define MBARRIER_INVAL(mbar) \
    asm volatile("mbarrier.inval.shared.b64 [%0];" :: "r"((uint32_t)(mbar)) : "memory")

#define MBARRIER_WAIT_PARITY(mbar_addr, phase_parity) do { \
    uint32_t _mbar = (uint32_t)(mbar_addr); \
    uint32_t _parity = (uint32_t)(phase_parity); \
    uint32_t _done; \
    asm volatile( \
        "{\n\t.reg .pred p;\n\t" \
        "mbarrier.try_wait.parity.acquire.cta.shared::cta.b64 p, [%1], %2;\n\t" \
        "selp.b32 %0, 1, 0, p;\n\t}" \
        : "=r"(_done) : "r"(_mbar), "r"(_parity) : "memory"); \
    if (!_done) { \
        asm volatile( \
            "{\n\t.reg .pred P1;\n\t" \
            "WAIT_LOOP_%=:\n\t" \
            "mbarrier.try_wait.parity.acquire.cta.shared::cta.b64 P1, [%0], %1, 0x989680;\n\t" \
            "@P1 bra.uni WAIT_DONE_%=;\n\t" \
            "bra.uni WAIT_LOOP_%=;\n\t" \
            "WAIT_DONE_%=:\n\t}" \
            :: "r"(_mbar), "r"(_parity) : "memory"); \
    } \
} while(0)

#define TCGEN05_LD_32X32B_X32(r, tmem_addr) \
    asm volatile( \
        "tcgen05.ld.sync.aligned.32x32b.x32.b32 " \
        "{%0, %1, %2, %3, %4, %5, %6, %7, " \
        " %8, %9, %10, %11, %12, %13, %14, %15, " \
        " %16, %17, %18, %19, %20, %21, %22, %23, " \
        " %24, %25, %26, %27, %28, %29, %30, %31}, [%32];" \
        : "=r"((r)[0]),  "=r"((r)[1]),  "=r"((r)[2]),  "=r"((r)[3]), \
          "=r"((r)[4]),  "=r"((r)[5]),  "=r"((r)[6]),  "=r"((r)[7]), \
          "=r"((r)[8]),  "=r"((r)[9]),  "=r"((r)[10]), "=r"((r)[11]), \
          "=r"((r)[12]), "=r"((r)[13]), "=r"((r)[14]), "=r"((r)[15]), \
          "=r"((r)[16]), "=r"((r)[17]), "=r"((r)[18]), "=r"((r)[19]), \
          "=r"((r)[20]), "=r"((r)[21]), "=r"((r)[22]), "=r"((r)[23]), \
          "=r"((r)[24]), "=r"((r)[25]), "=r"((r)[26]), "=r"((r)[27]), \
          "=r"((r)[28]), "=r"((r)[29]), "=r"((r)[30]), "=r"((r)[31]) \
        : "r"(tmem_addr))

#define TCGEN05_ST_32X32B_X32(tmem_addr, r) \
    asm volatile( \
        "tcgen05.st.sync.aligned.32x32b.x32.b32 [%0], " \
        "{%1, %2, %3, %4, %5, %6, %7, %8, " \
        " %9, %10, %11, %12, %13, %14, %15, %16, " \
        " %17, %18, %19, %20, %21, %22, %23, %24, " \
        " %25, %26, %27, %28, %29, %30, %31, %32};" \
        :: "r"(tmem_addr), \
           "r"((r)[0]),  "r"((r)[1]),  "r"((r)[2]),  "r"((r)[3]), \
           "r"((r)[4]),  "r"((r)[5]),  "r"((r)[6]),  "r"((r)[7]), \
           "r"((r)[8]),  "r"((r)[9]),  "r"((r)[10]), "r"((r)[11]), \
           "r"((r)[12]), "r"((r)[13]), "r"((r)[14]), "r"((r)[15]), \
           "r"((r)[16]), "r"((r)[17]), "r"((r)[18]), "r"((r)[19]), \
           "r"((r)[20]), "r"((r)[21]), "r"((r)[22]), "r"((r)[23]), \
           "r"((r)[24]), "r"((r)[25]), "r"((r)[26]), "r"((r)[27]), \
           "r"((r)[28]), "r"((r)[29]), "r"((r)[30]), "r"((r)[31]) \
        : "memory")

// SW128 smem descriptor: layout=2(SW128), version=1, SBO=64 (1024B), LBO=1 (16B)
static constexpr uint64_t SMEM_DESC_BASE_SW128 =
    (uint64_t(2)  << 61) | (uint64_t(1) << 46) | (uint64_t(64) << 32) | (uint64_t(1) << 16);
#define MAKE_SMEM_DESC(base_addr) \
    (SMEM_DESC_BASE_SW128 | ((uint64_t)((base_addr) >> 4) & 0x3FFF))

// tf32 SS MMA (A in SMEM)
__device__ __forceinline__ void mma_tf32_ss(uint32_t d, uint64_t ad, uint64_t bd,
                                            uint32_t idesc, bool acc) {
    uint32_t en = acc ? 1u : 0u;
    asm volatile(
        "{\n\t.reg .pred p;\n\tsetp.ne.u32 p, %5, 0;\n\t"
        "tcgen05.mma.cta_group::1.kind::tf32 [%0], %1, %2, %3, {%4, %4, %4, %4}, p;\n\t}"
        :: "r"(d), "l"(ad), "l"(bd), "r"(idesc), "r"(0u), "r"(en)
        : "memory");
}
// tf32 TS MMA (A in TMEM)
__device__ __forceinline__ void mma_tf32_ts(uint32_t d, uint32_t a_tmem, uint64_t bd,
                                            uint32_t idesc, bool acc) {
    uint32_t en = acc ? 1u : 0u;
    asm volatile(
        "{\n\t.reg .pred p;\n\tsetp.ne.u32 p, %5, 0;\n\t"
        "tcgen05.mma.cta_group::1.kind::tf32 [%0], [%1], %2, %3, {%4, %4, %4, %4}, p;\n\t}"
        :: "r"(d), "r"(a_tmem), "l"(bd), "r"(idesc), "r"(0u), "r"(en)
        : "memory");
}

// idesc: c=F32(1@4), a=TF32(2@7), b=TF32(2@10), N@17 (N/8), M@24 (M/16)
static constexpr uint32_t IDESC_TF32_128x128 =
    (1u << 4) | (2u << 7) | (2u << 10) | ((128u / 8u) << 17) | ((128u / 16u) << 24);
static constexpr uint32_t IDESC_TF32_128x64 =
    (1u << 4) | (2u << 7) | (2u << 10) | ((64u / 8u) << 17) | ((128u / 16u) << 24);
#endif  // TC_OK

#define SMEM_SWIZZLE_128B(off) ((off) ^ (((off) >> 3) & 0x70))

// round-to-nearest tf32 (fp32 with low mantissa zeroed) — any target
__device__ __forceinline__ float tf32_rna(float x) {
    uint32_t u;
    asm("cvt.rna.tf32.f32 %0, %1;" : "=r"(u) : "f"(x));
    return __uint_as_float(u);
}

// blocked-atom SW128 byte offset for a [rows x ncolsK] fp32 K-major tile:
// atom = 8 rows x 32 floats (1024B); atom index = (row/8) + (col/32)*(rows/8)
__device__ __forceinline__ uint32_t qk_off(int row, int col, int rows) {
    uint32_t byte = (uint32_t)((row >> 3) + (col >> 5) * (rows >> 3)) * 1024u
                  + (uint32_t)(row & 7) * 128u + (uint32_t)(col & 31) * 4u;
    return SMEM_SWIZZLE_128B(byte);
}

// ============================================================================
// Weight transpose: out[C][R] = in[R][C]
// ============================================================================
__global__ void transpose_kernel(const float* __restrict__ in, float* __restrict__ out,
                                 int R, int C)
{
    __shared__ float t[32][33];
    int bx = blockIdx.x * 32;
    int by = blockIdx.y * 32;
    int x = bx + threadIdx.x;
#pragma unroll
    for (int j = 0; j < 32; j += 8)
        t[threadIdx.y + j][threadIdx.x] = in[(size_t)(by + threadIdx.y + j) * C + x];
    __syncthreads();
    int x2 = by + threadIdx.x;
#pragma unroll
    for (int j = 0; j < 32; j += 8)
        out[(size_t)(bx + threadIdx.y + j) * R + x2] = t[threadIdx.x][threadIdx.y + j];
}

// ============================================================================
// GEMM: C[M,N] = A[M,K] @ BT[N,K]^T + bias[N]  (round-4 kernel, unchanged)
// ============================================================================
constexpr int GT_TILE_BYTES  = 128 * 32 * 4;
constexpr int GT_STAGE_BYTES = 4 * GT_TILE_BYTES;
constexpr int GT_SMEM_TILES0 = 1024;
constexpr int GT_SMEM_TOTAL  = GT_SMEM_TILES0 + 2 * GT_STAGE_BYTES;  // 132096
constexpr int GT_TMEM_COLS   = 128;

template<bool SCATTER>
__device__ __forceinline__ void gemm_epilogue_store(
    const float* __restrict__ buf, const float* __restrict__ bias,
    float* __restrict__ C, int m0, int n0, int N, int tid)
{
#pragma unroll
    for (int i = 0; i < 16; i++) {
        int g  = tid + i * 256;
        int r  = g >> 5;
        int c4 = (g & 31) * 4;
        const float* row = buf + (size_t)r * 132 + c4;
        int n = n0 + c4;
        float4 bv = *(const float4*)(bias + n);
        float4 v;
        v.x = row[0] + bv.x; v.y = row[1] + bv.y;
        v.z = row[2] + bv.z; v.w = row[3] + bv.w;
        int m = m0 + r;
        if (!SCATTER) {
            *(float4*)(C + (size_t)m * N + n) = v;
        } else {
            int part = n / cfg::D;
            int dn   = n - part * cfg::D;
            int h    = dn >> 6;
            int c    = dn & 63;
            int b_   = m >> 11;
            int s_   = m & 2047;
            float* dst = (part == 0) ? g_Q : (part == 1) ? g_K : g_V;
            *(float4*)(dst + ((size_t)(b_ * cfg::H + h) * cfg::S + s_) * cfg::HD + c) = v;
        }
    }
}

template<bool SCATTER>
__global__ void __launch_bounds__(256) gemm_tf32_kernel(
    const float* __restrict__ A, const float* __restrict__ BT,
    const float* __restrict__ bias, float* __restrict__ C,
    int M, int N, int K)
{
    extern __shared__ char smem[];
    const int tid = threadIdx.x;
    const int m0  = blockIdx.y * 128;
    const int n0  = blockIdx.x * 128;

#if TC_OK
    const uint32_t smem_base = smem_to_u32(smem);
    const uint32_t mbar0 = smem_base + 16;
    const uint32_t mbar1 = smem_base + 24;
    const int wid = tid >> 5;
    const int lid = tid & 31;

    if (wid == 0) TCGEN05_ALLOC(smem_base, GT_TMEM_COLS);
    if (tid == 0) {
        MBARRIER_INIT(mbar0, 1);
        MBARRIER_INIT(mbar1, 1);
    }
    __syncthreads();
    uint32_t tmem;
    asm volatile("ld.shared.b32 %0, [%1];" : "=r"(tmem) : "r"(smem_base));

    const int T = K / 32;
    int ph0 = 0, ph1 = 0;

    for (int t = 0; t < T; t++) {
        const int s = t & 1;
        const uint32_t stage = smem_base + GT_SMEM_TILES0 + s * GT_STAGE_BYTES;
        const uint32_t Ah = stage;
        const uint32_t Al = stage + GT_TILE_BYTES;
        const uint32_t Bh = stage + 2 * GT_TILE_BYTES;
        const uint32_t Bl = stage + 3 * GT_TILE_BYTES;

        if (t >= 2) {
            if (s == 0) { MBARRIER_WAIT_PARITY(mbar0, ph0); ph0 ^= 1; }
            else        { MBARRIER_WAIT_PARITY(mbar1, ph1); ph1 ^= 1; }
        }

        const int k0 = t * 32;
#pragma unroll
        for (int i = 0; i < 4; i++) {
            int g  = tid + i * 256;
            int r  = g >> 3;
            int c4 = (g & 7) * 4;
            float4 v = *(const float4*)(A + (size_t)(m0 + r) * K + k0 + c4);
            float4 vh, vl;
            vh.x = tf32_rna(v.x); vl.x = tf32_rna(v.x - vh.x);
            vh.y = tf32_rna(v.y); vl.y = tf32_rna(v.y - vh.y);
            vh.z = tf32_rna(v.z); vl.z = tf32_rna(v.z - vh.z);
            vh.w = tf32_rna(v.w); vl.w = tf32_rna(v.w - vh.w);
            uint32_t off = SMEM_SWIZZLE_128B((uint32_t)(r * 128 + c4 * 4));
            *(float4*)(smem + (Ah - smem_base) + off) = vh;
            *(float4*)(smem + (Al - smem_base) + off) = vl;
        }
#pragma unroll
        for (int i = 0; i < 4; i++) {
            int g  = tid + i * 256;
            int r  = g >> 3;
            int c4 = (g & 7) * 4;
            float4 v = *(const float4*)(BT + (size_t)(n0 + r) * K + k0 + c4);
            float4 vh, vl;
            vh.x = tf32_rna(v.x); vl.x = tf32_rna(v.x - vh.x);
            vh.y = tf32_rna(v.y); vl.y = tf32_rna(v.y - vh.y);
            vh.z = tf32_rna(v.z); vl.z = tf32_rna(v.z - vh.z);
            vh.w = tf32_rna(v.w); vl.w = tf32_rna(v.w - vh.w);
            uint32_t off = SMEM_SWIZZLE_128B((uint32_t)(r * 128 + c4 * 4));
            *(float4*)(smem + (Bh - smem_base) + off) = vh;
            *(float4*)(smem + (Bl - smem_base) + off) = vl;
        }
        __syncthreads();

        if (wid == 0) {
            if (elect_one_pred()) {
                FENCE_PROXY_ASYNC();
                uint64_t dah = MAKE_SMEM_DESC(Ah);
                uint64_t dal = MAKE_SMEM_DESC(Al);
                uint64_t dbh = MAKE_SMEM_DESC(Bh);
                uint64_t dbl = MAKE_SMEM_DESC(Bl);
#pragma unroll
                for (int j = 0; j < 4; j++) {
                    uint64_t oj = (uint64_t)(j * 2);
                    mma_tf32_ss(tmem, dah + oj, dbh + oj, IDESC_TF32_128x128,
                                !(t == 0 && j == 0));
                    mma_tf32_ss(tmem, dal + oj, dbh + oj, IDESC_TF32_128x128, true);
                    mma_tf32_ss(tmem, dah + oj, dbl + oj, IDESC_TF32_128x128, true);
                }
                TCGEN05_COMMIT(s == 0 ? mbar0 : mbar1);
            }
        }
    }

    MBARRIER_WAIT_PARITY(mbar0, ph0);
    MBARRIER_WAIT_PARITY(mbar1, ph1);
    TCGEN05_FENCE_AFTER();

    float* buf = (float*)(smem + GT_SMEM_TILES0);   // [128][132]
    if (wid < 4) {
#pragma unroll
        for (int b = 0; b < 4; b++) {
            uint32_t regs[32];
            TCGEN05_LD_32X32B_X32(regs, tmem + b * 32);
            TCGEN05_WAIT_LD();
            float* row = buf + (size_t)(wid * 32 + lid) * 132 + b * 32;
#pragma unroll
            for (int c = 0; c < 32; c++) row[c] = __uint_as_float(regs[c]);
        }
        TCGEN05_FENCE_BEFORE();
    }
    __syncthreads();

    gemm_epilogue_store<SCATTER>(buf, bias, C, m0, n0, N, tid);

    __syncthreads();
    if (tid == 0) { MBARRIER_INVAL(mbar0); MBARRIER_INVAL(mbar1); }
    __syncthreads();
    if (wid == 0) {
        TCGEN05_RELINQUISH();
        TCGEN05_DEALLOC(tmem, GT_TMEM_COLS);
    }

#else
    // fp32 fallback (compile-only on non-'a' pass)
    float* As = (float*)smem;
    float* Bs = As + 2 * 8 * 128;
    const int tx = tid & 15;
    const int ty = tid >> 4;
    const int lr = tid >> 1;
    const int lk = (tid & 1) * 4;

    float acc[8][8];
#pragma unroll
    for (int i = 0; i < 8; i++)
#pragma unroll
        for (int j = 0; j < 8; j++) acc[i][j] = 0.f;

    float4 av = *(const float4*)(A  + (size_t)(m0 + lr) * K + lk);
    float4 bv = *(const float4*)(BT + (size_t)(n0 + lr) * K + lk);
    As[(lk + 0) * 128 + lr] = av.x; As[(lk + 1) * 128 + lr] = av.y;
    As[(lk + 2) * 128 + lr] = av.z; As[(lk + 3) * 128 + lr] = av.w;
    Bs[(lk + 0) * 128 + lr] = bv.x; Bs[(lk + 1) * 128 + lr] = bv.y;
    Bs[(lk + 2) * 128 + lr] = bv.z; Bs[(lk + 3) * 128 + lr] = bv.w;
    __syncthreads();

    int buf = 0;
    for (int k0 = 0; k0 < K; k0 += 8) {
        const bool more = (k0 + 8) < K;
        if (more) {
            av = *(const float4*)(A  + (size_t)(m0 + lr) * K + (k0 + 8 + lk));
            bv = *(const float4*)(BT + (size_t)(n0 + lr) * K + (k0 + 8 + lk));
        }
        const float* Ab = As + buf * 8 * 128;
        const float* Bb = Bs + buf * 8 * 128;
#pragma unroll
        for (int kk = 0; kk < 8; kk++) {
            float a[8], b[8];
#pragma unroll
            for (int i = 0; i < 4; i++) {
                a[i]     = Ab[kk * 128 + ty * 4 + i];
                a[i + 4] = Ab[kk * 128 + 64 + ty * 4 + i];
                b[i]     = Bb[kk * 128 + tx * 4 + i];
                b[i + 4] = Bb[kk * 128 + 64 + tx * 4 + i];
            }
#pragma unroll
            for (int i = 0; i < 8; i++)
#pragma unroll
                for (int j = 0; j < 8; j++) acc[i][j] += a[i] * b[j];
        }
        if (more) {
            float* An = As + (buf ^ 1) * 8 * 128;
            float* Bn = Bs + (buf ^ 1) * 8 * 128;
            An[(lk + 0) * 128 + lr] = av.x; An[(lk + 1) * 128 + lr] = av.y;
            An[(lk + 2) * 128 + lr] = av.z; An[(lk + 3) * 128 + lr] = av.w;
            Bn[(lk + 0) * 128 + lr] = bv.x; Bn[(lk + 1) * 128 + lr] = bv.y;
            Bn[(lk + 2) * 128 + lr] = bv.z; Bn[(lk + 3) * 128 + lr] = bv.w;
        }
        __syncthreads();
        buf ^= 1;
    }

#pragma unroll
    for (int i = 0; i < 8; i++) {
        int m = m0 + ((i < 4) ? (ty * 4 + i) : (64 + ty * 4 + (i - 4)));
#pragma unroll
        for (int jh = 0; jh < 2; jh++) {
            int n = n0 + jh * 64 + tx * 4;
            float4 r;
            r.x = acc[i][jh * 4 + 0] + bias[n + 0];
            r.y = acc[i][jh * 4 + 1] + bias[n + 1];
            r.z = acc[i][jh * 4 + 2] + bias[n + 2];
            r.w = acc[i][jh * 4 + 3] + bias[n + 3];
            if (!SCATTER) {
                *(float4*)(C + (size_t)m * N + n) = r;
            } else {
                int part = n / cfg::D;
                int dn   = n - part * cfg::D;
                int h    = dn >> 6;
                int c    = dn & 63;
                int b_   = m >> 11;
                int s_   = m & 2047;
                float* dst = (part == 0) ? g_Q : (part == 1) ? g_K : g_V;
                *(float4*)(dst + ((size_t)(b_ * cfg::H + h) * cfg::S + s_) * cfg::HD + c) = r;
            }
        }
    }
#endif
}

// ============================================================================
// V suffix sums (exact masked-softmax mass)
// ============================================================================
__global__ void __launch_bounds__(512) suffix_kernel()
{
    __shared__ float tot[32][64];
    const int bh    = blockIdx.x;
    const int t     = threadIdx.x;
    const int lane4 = t & 15;
    const int seg   = t >> 4;
    const size_t base = (size_t)bh * cfg::S * cfg::HD;
    const float4* Vp = (const float4*)(g_V + base);
    float4* SVp = (float4*)(g_SV + base);

    const int r0 = seg * 64;
    float4 acc = make_float4(0.f, 0.f, 0.f, 0.f);
    for (int r = r0 + 63; r >= r0; r--) {
        float4 v = Vp[(size_t)r * 16 + lane4];
        acc.x += v.x; acc.y += v.y; acc.z += v.z; acc.w += v.w;
        SVp[(size_t)r * 16 + lane4] = acc;
    }
    *(float4*)&tot[seg][lane4 * 4] = acc;
    __syncthreads();

    float4 off = make_float4(0.f, 0.f, 0.f, 0.f);
    for (int s2 = seg + 1; s2 < 32; s2++) {
        float4 tv = *(const float4*)&tot[s2][lane4 * 4];
        off.x += tv.x; off.y += tv.y; off.z += tv.z; off.w += tv.w;
    }
    if (seg < 31) {
        for (int r = r0; r < r0 + 64; r++) {
            float4 v = SVp[(size_t)r * 16 + lane4];
            v.x += off.x; v.y += off.y; v.z += off.z; v.w += off.w;
            SVp[(size_t)r * 16 + lane4] = v;
        }
    }
}

// ============================================================================
// Flash attention on tcgen05 (tf32 3x split), EXACT reference mask semantics.
// CTA = (bh, 128 q rows), 128 threads (4 warps). 64-key blocks.
//   S = Q K^T  : SS mode, M=128 N=64 K=64
//   P -> TMEM  : STTM tf32 hi/lo (TS-mode A operand)
//   O = P V    : TS mode, M=128 N=64 K=64; O rescaled in registers per block
// Masked softmax mass added exactly via V suffix sums in the epilogue.
// ============================================================================
constexpr int AT_QH   = 1024;
constexpr int AT_QL   = AT_QH + 32768;                // Q tiles 32KB each
constexpr int AT_KV0  = AT_QL + 32768;                // 66560
constexpr int AT_STAGE = 65536;                       // KH,KL,VTH,VTL 16KB each
constexpr int AT_SMEM  = AT_KV0 + 2 * AT_STAGE;       // 197632
constexpr int AT_SMEM_FALLBACK = (128*65 + 64*65 + 64*65 + 128*65) * 4;

__global__ void __launch_bounds__(128) attn_kernel()
{
    extern __shared__ char smem[];
#if TC_OK
    const uint32_t smem_base = smem_to_u32(smem);
    const uint32_t mbar = smem_base + 8;
    const int tid = threadIdx.x;
    const int wid = tid >> 5;
    const int lid = tid & 31;
    const uint32_t warp_off = (uint32_t)wid << 21;

    const int qb = (int)gridDim.x - 1 - (int)blockIdx.x;  // heavy tiles first
    const int bh = blockIdx.y;
    const int b  = bh / cfg::H;
    const int h  = bh % cfg::H;
    const size_t base = (size_t)bh * cfg::S * cfg::HD;

    if (wid == 0) TCGEN05_ALLOC(smem_base, 256);
    if (tid == 0) MBARRIER_INIT(mbar, 1);
    __syncthreads();
    uint32_t tmem;
    asm volatile("ld.shared.b32 %0, [%1];" : "=r"(tmem) : "r"(smem_base));
    const uint32_t T_S  = tmem;          // 64 cols: scores
    const uint32_t T_PH = tmem + 64;     // 64 cols: P hi
    const uint32_t T_PL = tmem + 128;    // 64 cols: P lo
    const uint32_t T_O  = tmem + 192;    // 64 cols: O block result

    // ---- load Q tile (hi/lo, blocked SW128 atoms, rows=128) ----
    {
        const float* Qg = g_Q + base + (size_t)qb * 128 * 64;
#pragma unroll
        for (int i = 0; i < 16; i++) {
            int g  = tid + i * 128;
            int r  = g >> 4;
            int c4 = (g & 15) * 4;
            float4 v = *(const float4*)(Qg + (size_t)r * 64 + c4);
            float4 vh, vl;
            vh.x = tf32_rna(v.x); vl.x = tf32_rna(v.x - vh.x);
            vh.y = tf32_rna(v.y); vl.y = tf32_rna(v.y - vh.y);
            vh.z = tf32_rna(v.z); vl.z = tf32_rna(v.z - vh.z);
            vh.w = tf32_rna(v.w); vl.w = tf32_rna(v.w - vh.w);
            uint32_t off = qk_off(r, c4, 128);
            *(float4*)(smem + AT_QH + off) = vh;
            *(float4*)(smem + AT_QL + off) = vl;
        }
    }

    // ---- KV loader for one 64-key block into stage st ----
    auto load_kv = [&](int kb, int st) {
        const int stage = AT_KV0 + st * AT_STAGE;
        const float* Kg = g_K + base + (size_t)kb * 64 * 64;
        const float* Vg = g_V + base + (size_t)kb * 64 * 64;
#pragma unroll
        for (int i = 0; i < 8; i++) {
            int g   = tid + i * 128;
            int key = g >> 4;
            int c4  = (g & 15) * 4;
            float4 v = *(const float4*)(Kg + (size_t)key * 64 + c4);
            float4 vh, vl;
            vh.x = tf32_rna(v.x); vl.x = tf32_rna(v.x - vh.x);
            vh.y = tf32_rna(v.y); vl.y = tf32_rna(v.y - vh.y);
            vh.z = tf32_rna(v.z); vl.z = tf32_rna(v.z - vh.z);
            vh.w = tf32_rna(v.w); vl.w = tf32_rna(v.w - vh.w);
            uint32_t off = qk_off(key, c4, 64);
            *(float4*)(smem + stage + off) = vh;                 // KH
            *(float4*)(smem + stage + 16384 + off) = vl;         // KL
        }
#pragma unroll
        for (int i = 0; i < 8; i++) {
            int g   = tid + i * 128;
            int key = g >> 4;
            int c4  = (g & 15) * 4;
            float4 v = *(const float4*)(Vg + (size_t)key * 64 + c4);
            float vv[4] = {v.x, v.y, v.z, v.w};
#pragma unroll
            for (int q = 0; q < 4; q++) {       // transpose: VT[d][key]
                float hi = tf32_rna(vv[q]);
                float lo = tf32_rna(vv[q] - hi);
                uint32_t off = qk_off(c4 + q, key, 64);
                *(float*)(smem + stage + 32768 + off) = hi;      // VTH
                *(float*)(smem + stage + 49152 + off) = lo;      // VTL
            }
        }
    };

    load_kv(0, 0);
    __syncthreads();

    float o[64];
#pragma unroll
    for (int c = 0; c < 64; c++) o[c] = 0.f;
    float mi = -1e30f, li = 0.f;
    const int qg = qb * 128 + wid * 32 + lid;   // this thread's q row

    int ph = 0;
    int st = 0;
    const int nkb = 2 * qb + 2;

    for (int kb = 0; kb < nkb; kb++) {
        const uint32_t stage = smem_base + AT_KV0 + st * AT_STAGE;

        // ---- issue S = Q K^T (warp 0) ----
        if (wid == 0) {
            TCGEN05_FENCE_AFTER();
            if (elect_one_pred()) {
                FENCE_PROXY_ASYNC();
                uint64_t dqh = MAKE_SMEM_DESC(smem_base + AT_QH);
                uint64_t dql = MAKE_SMEM_DESC(smem_base + AT_QL);
                uint64_t dkh = MAKE_SMEM_DESC(stage);
                uint64_t dkl = MAKE_SMEM_DESC(stage + 16384);
#pragma unroll
                for (int j = 0; j < 8; j++) {
                    uint64_t qo = (uint64_t)((j >> 2) * 1024 + (j & 3) * 2);
                    uint64_t ko = (uint64_t)((j >> 2) * 512  + (j & 3) * 2);
                    mma_tf32_ss(T_S, dqh + qo, dkh + ko, IDESC_TF32_128x64, j != 0);
                    mma_tf32_ss(T_S, dql + qo, dkh + ko, IDESC_TF32_128x64, true);
                    mma_tf32_ss(T_S, dqh + qo, dkl + ko, IDESC_TF32_128x64, true);
                }
                TCGEN05_COMMIT(mbar);
            }
        }

        // ---- prefetch next KV block (overlaps S MMA) ----
        if (kb + 1 < nkb) load_kv(kb + 1, st ^ 1);

        // ---- wait S, softmax ----
        MBARRIER_WAIT_PARITY(mbar, ph); ph ^= 1;
        TCGEN05_FENCE_AFTER();

        uint32_t su[64];
        TCGEN05_LD_32X32B_X32(su, T_S + warp_off);
        TCGEN05_LD_32X32B_X32(su + 32, T_S + 32 + warp_off);
        TCGEN05_WAIT_LD();

        const int kg0 = kb * 64;
        const bool diag = (kg0 + 63 > qg);
        float mloc = -1e30f;
#pragma unroll
        for (int j = 0; j < 64; j++) {
            float v = __uint_as_float(su[j]);
            if (diag && (kg0 + j > qg)) v = -1e30f;
            su[j] = __float_as_uint(v);
            mloc = fmaxf(mloc, v);
        }
        float mnew = fmaxf(mi, mloc);
        float corr = __expf(mi - mnew);
        float ps = 0.f;
#pragma unroll
        for (int ch = 0; ch < 2; ch++) {
            uint32_t phv[32], plv[32];
#pragma unroll
            for (int j = 0; j < 32; j++) {
                float p = __expf(__uint_as_float(su[ch * 32 + j]) - mnew);
                ps += p;
                float hi = tf32_rna(p);
                float lo = tf32_rna(p - hi);
                phv[j] = __float_as_uint(hi);
                plv[j] = __float_as_uint(lo);
            }
            TCGEN05_ST_32X32B_X32(T_PH + ch * 32 + warp_off, phv);
            TCGEN05_ST_32X32B_X32(T_PL + ch * 32 + warp_off, plv);
        }
        TCGEN05_WAIT_ST();
        li = li * corr + ps;
        mi = mnew;
        TCGEN05_FENCE_BEFORE();
        __syncthreads();

        // ---- issue O = P V (warp 0, TS mode) ----
        if (wid == 0) {
            TCGEN05_FENCE_AFTER();
            if (elect_one_pred()) {
                FENCE_PROXY_ASYNC();
                uint64_t dvh = MAKE_SMEM_DESC(stage + 32768);
                uint64_t dvl = MAKE_SMEM_DESC(stage + 49152);
#pragma unroll
                for (int j = 0; j < 8; j++) {
                    uint64_t vo = (uint64_t)((j >> 2) * 512 + (j & 3) * 2);
                    mma_tf32_ts(T_O, T_PH + j * 8, dvh + vo, IDESC_TF32_128x64, j != 0);
                    mma_tf32_ts(T_O, T_PL + j * 8, dvh + vo, IDESC_TF32_128x64, true);
                    mma_tf32_ts(T_O, T_PH + j * 8, dvl + vo, IDESC_TF32_128x64, true);
                }
                TCGEN05_COMMIT(mbar);
            }
        }

        MBARRIER_WAIT_PARITY(mbar, ph); ph ^= 1;
        TCGEN05_FENCE_AFTER();

        // ---- accumulate O with rescale ----
#pragma unroll
        for (int ch = 0; ch < 2; ch++) {
            uint32_t tv[32];
            TCGEN05_LD_32X32B_X32(tv, T_O + ch * 32 + warp_off);
            TCGEN05_WAIT_LD();
#pragma unroll
            for (int j = 0; j < 32; j++)
                o[ch * 32 + j] = o[ch * 32 + j] * corr + __uint_as_float(tv[j]);
        }
        st ^= 1;
    }

    // ---- epilogue: exact masked mass, normalize, write row ----
    {
        float e   = __expf(1e-9f - mi);
        float cnt = (float)(cfg::S - 1 - qg);
        float inv = 1.0f / (li + cnt * e);
        float* outp = g_A + ((size_t)(b * cfg::S + qg)) * cfg::D + h * cfg::HD;
        const float* svp = (qg + 1 < cfg::S)
                         ? g_SV + base + (size_t)(qg + 1) * cfg::HD : nullptr;
#pragma unroll
        for (int c4 = 0; c4 < 64; c4 += 4) {
            float4 sv = svp ? *(const float4*)(svp + c4)
                            : make_float4(0.f, 0.f, 0.f, 0.f);
            float4 r;
            r.x = (o[c4 + 0] + e * sv.x) * inv;
            r.y = (o[c4 + 1] + e * sv.y) * inv;
            r.z = (o[c4 + 2] + e * sv.z) * inv;
            r.w = (o[c4 + 3] + e * sv.w) * inv;
            *(float4*)(outp + c4) = r;
        }
    }

    __syncthreads();
    if (tid == 0) MBARRIER_INVAL(mbar);
    __syncthreads();
    if (wid == 0) {
        TCGEN05_RELINQUISH();
        TCGEN05_DEALLOC(tmem, 256);
    }

#else
    // fp32 fallback (compile-only on non-'a' pass; never executed on GB300)
    float* Qs = (float*)smem;
    float* Ks = Qs + 128 * 65;
    float* Vs = Ks + 64 * 65;
    float* Ps = Vs + 64 * 65;

    const int qb = (int)gridDim.x - 1 - (int)blockIdx.x;
    const int bh = blockIdx.y;
    const int b  = bh / cfg::H;
    const int h  = bh % cfg::H;
    const size_t base = (size_t)bh * cfg::S * cfg::HD;

    const int tid = threadIdx.x;
    const int tx  = tid & 15;
    const int ty  = tid >> 4;   // 0..7 with 128 threads -> 8 row groups of 16

    for (int i = tid; i < 128 * 16; i += 128) {
        int r  = i >> 4;
        int c4 = (i & 15) << 2;
        float4 t = *(const float4*)(g_Q + base + (size_t)(qb * 128 + r) * cfg::HD + c4);
        float* q = &Qs[r * 65 + c4];
        q[0] = t.x; q[1] = t.y; q[2] = t.z; q[3] = t.w;
    }

    float o[16][4];
    float mi[16], li[16];
#pragma unroll
    for (int i = 0; i < 16; i++) {
        mi[i] = -1e30f; li[i] = 0.f;
#pragma unroll
        for (int j = 0; j < 4; j++) o[i][j] = 0.f;
    }

    const int nkb = 2 * qb + 2;
    for (int kb = 0; kb < nkb; kb++) {
        __syncthreads();
        for (int i = tid; i < 64 * 16; i += 128) {
            int r  = i >> 4;
            int c4 = (i & 15) << 2;
            float4 tk = *(const float4*)(g_K + base + (size_t)(kb * 64 + r) * cfg::HD + c4);
            float4 tv = *(const float4*)(g_V + base + (size_t)(kb * 64 + r) * cfg::HD + c4);
            float* kd = &Ks[r * 65 + c4];
            kd[0] = tk.x; kd[1] = tk.y; kd[2] = tk.z; kd[3] = tk.w;
            float* vd = &Vs[r * 65 + c4];
            vd[0] = tv.x; vd[1] = tv.y; vd[2] = tv.z; vd[3] = tv.w;
        }
        __syncthreads();

        for (int half = 0; half < 2; half++) {
            float s[8][4];
#pragma unroll
            for (int i = 0; i < 8; i++)
#pragma unroll
                for (int j = 0; j < 4; j++) s[i][j] = 0.f;
            for (int d = 0; d < 64; d++) {
                float bk[4];
#pragma unroll
                for (int j = 0; j < 4; j++) bk[j] = Ks[(tx * 4 + j) * 65 + d];
#pragma unroll
                for (int i = 0; i < 8; i++) {
                    float aq = Qs[(half * 64 + ty * 8 + i) * 65 + d];
#pragma unroll
                    for (int j = 0; j < 4; j++) s[i][j] += aq * bk[j];
                }
            }
#pragma unroll
            for (int i = 0; i < 8; i++) {
                int ii = half * 8 + i;
                int qgr = qb * 128 + half * 64 + ty * 8 + i;
#pragma unroll
                for (int j = 0; j < 4; j++) {
                    int kg = kb * 64 + tx * 4 + j;
                    if (kg > qgr) s[i][j] = -1e30f;
                }
                float mloc = fmaxf(fmaxf(s[i][0], s[i][1]), fmaxf(s[i][2], s[i][3]));
                mloc = fmaxf(mloc, __shfl_xor_sync(0xffffffffu, mloc, 8, 16));
                mloc = fmaxf(mloc, __shfl_xor_sync(0xffffffffu, mloc, 4, 16));
                mloc = fmaxf(mloc, __shfl_xor_sync(0xffffffffu, mloc, 2, 16));
                mloc = fmaxf(mloc, __shfl_xor_sync(0xffffffffu, mloc, 1, 16));
                float mnew = fmaxf(mi[ii], mloc);
                float corr = __expf(mi[ii] - mnew);
                float psum = 0.f;
#pragma unroll
                for (int j = 0; j < 4; j++) {
                    float p = __expf(s[i][j] - mnew);
                    Ps[(half * 64 + ty * 8 + i) * 65 + tx * 4 + j] = p;
                    psum += p;
                }
                psum += __shfl_xor_sync(0xffffffffu, psum, 8, 16);
                psum += __shfl_xor_sync(0xffffffffu, psum, 4, 16);
                psum += __shfl_xor_sync(0xffffffffu, psum, 2, 16);
                psum += __shfl_xor_sync(0xffffffffu, psum, 1, 16);
                li[ii] = li[ii] * corr + psum;
                mi[ii] = mnew;
                o[ii][0] *= corr; o[ii][1] *= corr; o[ii][2] *= corr; o[ii][3] *= corr;
            }
            __syncwarp();
            for (int c = 0; c < 64; c++) {
                float vv[4];
#pragma unroll
                for (int j = 0; j < 4; j++) vv[j] = Vs[c * 65 + tx * 4 + j];
#pragma unroll
                for (int i = 0; i < 8; i++) {
                    float p = Ps[(half * 64 + ty * 8 + i) * 65 + c];
#pragma unroll
                    for (int j = 0; j < 4; j++) o[half * 8 + i][j] += p * vv[j];
                }
            }
        }
    }

#pragma unroll
    for (int ii = 0; ii < 16; ii++) {
        int half = ii >> 3, i = ii & 7;
        int qgr = qb * 128 + half * 64 + ty * 8 + i;
        float e   = __expf(1e-9f - mi[ii]);
        float cnt = (float)(cfg::S - 1 - qgr);
        float denom = li[ii] + cnt * e;
        float sv0 = 0.f, sv1 = 0.f, sv2 = 0.f, sv3 = 0.f;
        if (qgr + 1 < cfg::S) {
            const float* svp = g_SV + base + (size_t)(qgr + 1) * cfg::HD + tx * 4;
            sv0 = svp[0]; sv1 = svp[1]; sv2 = svp[2]; sv3 = svp[3];
        }
        float inv = 1.0f / denom;
        float4 r;
        r.x = (o[ii][0] + e * sv0) * inv;
        r.y = (o[ii][1] + e * sv1) * inv;
        r.z = (o[ii][2] + e * sv2) * inv;
        r.w = (o[ii][3] + e * sv3) * inv;
        *(float4*)(g_A + ((size_t)(b * cfg::S + qgr)) * cfg::D + h * cfg::HD + tx * 4) = r;
    }
#endif
}

// ============================================================================
// launcher
// ============================================================================
extern "C" void kernel_launch(void* const* d_in, const int* in_sizes, int n_in,
                              void* d_out, int out_size)
{
    (void)in_sizes; (void)n_in; (void)out_size;
    const float* x      = (const float*)d_in[0];
    const float* w_attn = (const float*)d_in[1];
    const float* b_attn = (const float*)d_in[2];
    const float* w_proj = (const float*)d_in[3];
    const float* b_proj = (const float*)d_in[4];
    float* out = (float*)d_out;

    float *p_a = nullptr, *p_wta = nullptr, *p_wtp = nullptr;
    cudaGetSymbolAddress((void**)&p_a,   g_A);
    cudaGetSymbolAddress((void**)&p_wta, g_WTa);
    cudaGetSymbolAddress((void**)&p_wtp, g_WTp);

    cudaFuncSetAttribute(attn_kernel, cudaFuncAttributeMaxDynamicSharedMemorySize,
                         AT_SMEM);
    cudaFuncSetAttribute(gemm_tf32_kernel<true>,
                         cudaFuncAttributeMaxDynamicSharedMemorySize, GT_SMEM_TOTAL);
    cudaFuncSetAttribute(gemm_tf32_kernel<false>,
                         cudaFuncAttributeMaxDynamicSharedMemorySize, GT_SMEM_TOTAL);

    // 0) weight transposes (BT layout: [N][K], K-major)
    transpose_kernel<<<dim3(cfg::NQKV / 32, cfg::D / 32), dim3(32, 8)>>>(
        w_attn, p_wta, cfg::D, cfg::NQKV);
    transpose_kernel<<<dim3(cfg::D / 32, cfg::D / 32), dim3(32, 8)>>>(
        w_proj, p_wtp, cfg::D, cfg::D);

    // 1) qkv = x @ w_attn + b_attn, scattered into g_Q/g_K/g_V
    gemm_tf32_kernel<true><<<dim3(cfg::NQKV / 128, cfg::MTOK / 128), 256, GT_SMEM_TOTAL>>>(
        x, p_wta, b_attn, nullptr, cfg::MTOK, cfg::NQKV, cfg::D);

    // 2) V suffix sums
    suffix_kernel<<<cfg::BH, 512>>>();

    // 3) flash attention on tcgen05 (exact mask semantics)
    attn_kernel<<<dim3(cfg::S / 128, cfg::BH), 128, AT_SMEM>>>();

    // 4) out = A @ w_proj + b_proj
    gemm_tf32_kernel<false><<<dim3(cfg::D / 128, cfg::MTOK / 128), 256, GT_SMEM_TOTAL>>>(
        p_a, p_wtp, b_proj, out, cfg::MTOK, cfg::D, cfg::D);
}